// round 8
// baseline (speedup 1.0000x reference)
#include <cuda_runtime.h>
#include <cuda_bf16.h>
#include <cstdint>
#include <math.h>

#define LSEQ 4096
#define BATCH 2
#define DIMC 256
#define EPS_F 1e-5f

// ---------------- scratch (device globals) ----------------
__device__ float g_x   [BATCH*DIMC*LSEQ];
__device__ float g_z   [BATCH*DIMC*LSEQ];
__device__ float g_xc  [2][BATCH*DIMC*LSEQ];
__device__ float g_dbl [2][BATCH*32*LSEQ];
__device__ float g_dt  [2][BATCH*DIMC*LSEQ];
__device__ float g_P   [2][64*BATCH*DIMC*8];
__device__ float g_S   [2][64*BATCH*DIMC*8];
__device__ float g_Hi  [2][64*BATCH*DIMC*8];
__device__ float g_y   [2][BATCH*DIMC*LSEQ];
__device__ float g_skipT[BATCH*LSEQ*DIMC];   // input0 transposed to token-major fp32

// bf16 split activations / weights (token-major, K=256 contiguous)
__device__ __nv_bfloat16 g_s0h[BATCH*LSEQ*DIMC], g_s0l[BATCH*LSEQ*DIMC];
__device__ __nv_bfloat16 g_s1h[BATCH*LSEQ*DIMC], g_s1l[BATCH*LSEQ*DIMC];
__device__ __nv_bfloat16 g_ynh[6*LSEQ*DIMC],     g_ynl[6*LSEQ*DIMC];
__device__ __nv_bfloat16 g_oh [6*LSEQ*DIMC],     g_ol [6*LSEQ*DIMC];
__device__ __nv_bfloat16 g_wip_h[DIMC*DIMC], g_wip_l[DIMC*DIMC];
__device__ __nv_bfloat16 g_wiz_h[DIMC*DIMC], g_wiz_l[DIMC*DIMC];
__device__ __nv_bfloat16 g_wop_h[DIMC*DIMC], g_wop_l[DIMC*DIMC];
__device__ __nv_bfloat16 g_wc3_h[1200*DIMC], g_wc3_l[1200*DIMC];

__device__ __forceinline__ float sigmoidf_(float x){ return 1.f/(1.f+__expf(-x)); }
__device__ __forceinline__ float softplusf_(float x){ return x>20.f ? x : log1pf(__expf(x)); }

__device__ __forceinline__ void bf16split(float v, __nv_bfloat16& h, __nv_bfloat16& l) {
    h = __float2bfloat16(v);
    l = __float2bfloat16(v - __bfloat162float(h));
}

__device__ __forceinline__ uint32_t smem_u32(const void* p) {
    uint32_t a;
    asm("{ .reg .u64 t; cvta.to.shared.u64 t, %1; cvt.u32.u64 %0, t; }" : "=r"(a) : "l"(p));
    return a;
}
__device__ __forceinline__ void ldmx4(uint32_t* r, uint32_t addr) {
    asm volatile("ldmatrix.sync.aligned.m8n8.x4.shared.b16 {%0,%1,%2,%3}, [%4];"
        : "=r"(r[0]),"=r"(r[1]),"=r"(r[2]),"=r"(r[3]) : "r"(addr));
}
__device__ __forceinline__ void mma16816(float* d, const uint32_t* a, uint32_t b0, uint32_t b1) {
    asm volatile("mma.sync.aligned.m16n8k16.row.col.f32.bf16.bf16.f32 "
        "{%0,%1,%2,%3}, {%4,%5,%6,%7}, {%8,%9}, {%0,%1,%2,%3};"
        : "+f"(d[0]),"+f"(d[1]),"+f"(d[2]),"+f"(d[3])
        : "r"(a[0]),"r"(a[1]),"r"(a[2]),"r"(a[3]), "r"(b0),"r"(b1));
}

// ---------------- split-bf16 GEMM on tensor cores via mma.sync ----------------
// D[128 tok, 128 ch] = A[tok,256] * W[ch,256]^T, A/W pre-split hi/lo bf16 (3 passes).
// SMEM: 4 tiles [128][72] bf16 (K-chunk 64, +8 pad). 8 warps: (mw 0..3) x (nw 0..1),
// each warp 32(M) x 64(N) via m16n8k16.
#define EPT_XPOSE 0
#define EPT_SKIP  1
#define EPT_BIAS  2
#define TILE_B 18432

template<int EPT>
__global__ void __launch_bounds__(256, 2) tcgemm_k(
    const __nv_bfloat16* __restrict__ Ah, const __nv_bfloat16* __restrict__ Al,
    const __nv_bfloat16* __restrict__ Bh, const __nv_bfloat16* __restrict__ Bl,
    int bRows,
    float* __restrict__ outF, const float* __restrict__ bias,
    const float* __restrict__ skipT,
    __nv_bfloat16* __restrict__ Oh, __nv_bfloat16* __restrict__ Ol)
{
    extern __shared__ char smem[];
    const int tid = threadIdx.x, lane = tid & 31, warp = tid >> 5;
    const int mw = warp & 3, nw = warp >> 2;
    const int n0 = blockIdx.x * 128, tl0 = blockIdx.y * 128, zb = blockIdx.z;
    const long long t0 = (long long)zb * LSEQ + tl0;

    float acc[2][8][4];
    #pragma unroll
    for (int i = 0; i < 2; i++)
        #pragma unroll
        for (int j = 0; j < 8; j++)
            #pragma unroll
            for (int c = 0; c < 4; c++) acc[i][j][c] = 0.f;

    const uint32_t sbase = smem_u32(smem);
    // ldmatrix per-thread offsets
    const int a_row  = (lane & 7) + ((lane >> 3) & 1) * 8;
    const int a_kadd = (lane >> 4) * 8;
    const int b_row  = (lane & 7) + (lane >> 4) * 8;
    const int b_kadd = ((lane >> 3) & 1) * 8;
    const uint32_t aoffH = sbase + 0      + (uint32_t)((mw*32 + a_row)*72 + a_kadd) * 2;
    const uint32_t aoffL = aoffH + TILE_B;
    const uint32_t boffH = sbase + 2*TILE_B + (uint32_t)((nw*64 + b_row)*72 + b_kadd) * 2;
    const uint32_t boffL = boffH + TILE_B;

    const int lrow = tid >> 3, lc8 = (tid & 7) * 8;   // global-load: 32 rows per pass

    for (int kc = 0; kc < 4; kc++) {
        if (kc) __syncthreads();
        #pragma unroll
        for (int it = 0; it < 4; it++) {
            int row = lrow + it * 32;
            uint32_t so = (uint32_t)(row * 72 + lc8) * 2;
            *(uint4*)(smem + so)          = *(const uint4*)(Ah + (t0+row)*256 + kc*64 + lc8);
            *(uint4*)(smem + TILE_B + so) = *(const uint4*)(Al + (t0+row)*256 + kc*64 + lc8);
            uint4 vh = make_uint4(0u,0u,0u,0u), vl = make_uint4(0u,0u,0u,0u);
            if (n0 + row < bRows) {
                vh = *(const uint4*)(Bh + (size_t)(n0+row)*256 + kc*64 + lc8);
                vl = *(const uint4*)(Bl + (size_t)(n0+row)*256 + kc*64 + lc8);
            }
            *(uint4*)(smem + 2*TILE_B + so) = vh;
            *(uint4*)(smem + 3*TILE_B + so) = vl;
        }
        __syncthreads();

        #pragma unroll
        for (int ks = 0; ks < 4; ks++) {
            const uint32_t k2 = (uint32_t)(ks * 16) * 2;
            uint32_t aH[2][4], aL[2][4];
            #pragma unroll
            for (int i = 0; i < 2; i++) {
                ldmx4(aH[i], aoffH + i*16*144 + k2);
                ldmx4(aL[i], aoffL + i*16*144 + k2);
            }
            #pragma unroll
            for (int half = 0; half < 2; half++) {
                uint32_t bH[2][4], bL[2][4];
                #pragma unroll
                for (int gg = 0; gg < 2; gg++) {
                    int g = half*2 + gg;
                    ldmx4(bH[gg], boffH + g*16*144 + k2);
                    ldmx4(bL[gg], boffL + g*16*144 + k2);
                }
                #pragma unroll
                for (int i = 0; i < 2; i++)
                    #pragma unroll
                    for (int gg = 0; gg < 2; gg++)
                        #pragma unroll
                        for (int p = 0; p < 2; p++) {
                            int j8 = (half*2 + gg)*2 + p;
                            mma16816(acc[i][j8], aH[i], bH[gg][2*p], bH[gg][2*p+1]);
                            mma16816(acc[i][j8], aH[i], bL[gg][2*p], bL[gg][2*p+1]);
                            mma16816(acc[i][j8], aL[i], bH[gg][2*p], bH[gg][2*p+1]);
                        }
            }
        }
    }

    if (EPT == EPT_SKIP) {
        // token-major bf16 hi/lo with fp32 skip add (skipT token-major)
        #pragma unroll
        for (int i = 0; i < 2; i++)
            #pragma unroll
            for (int rr = 0; rr < 2; rr++) {
                int tok = tl0 + mw*32 + i*16 + (lane >> 2) + rr*8;
                size_t orow = ((size_t)zb * LSEQ + tok) * 256;
                size_t srow = ((size_t)(zb & 1) * LSEQ + tok) * 256;
                #pragma unroll
                for (int j8 = 0; j8 < 8; j8++) {
                    int n = n0 + nw*64 + j8*8 + 2*(lane & 3);
                    float2 sk = *(const float2*)(skipT + srow + n);
                    float v0 = acc[i][j8][rr*2+0] + sk.x;
                    float v1 = acc[i][j8][rr*2+1] + sk.y;
                    __nv_bfloat16 h0,l0,h1,l1;
                    bf16split(v0,h0,l0); bf16split(v1,h1,l1);
                    __nv_bfloat162 ph; ph.x = h0; ph.y = h1;
                    __nv_bfloat162 pl; pl.x = l0; pl.y = l1;
                    *(__nv_bfloat162*)(Oh + orow + n) = ph;
                    *(__nv_bfloat162*)(Ol + orow + n) = pl;
                }
            }
    } else {
        // channel-major fp32 via smem transpose (two 64-row halves)
        float* sbuf = (float*)smem;
        #pragma unroll 1
        for (int h = 0; h < 2; h++) {
            __syncthreads();
            if (nw == h) {
                #pragma unroll
                for (int i = 0; i < 2; i++)
                    #pragma unroll
                    for (int j8 = 0; j8 < 8; j8++)
                        #pragma unroll
                        for (int rr = 0; rr < 2; rr++) {
                            int tok = mw*32 + i*16 + (lane >> 2) + rr*8;
                            int nl = j8*8 + 2*(lane & 3);
                            sbuf[nl*132 + tok]     = acc[i][j8][rr*2+0];
                            sbuf[(nl+1)*132 + tok] = acc[i][j8][rr*2+1];
                        }
            }
            __syncthreads();
            int row = tid >> 2;
            int n = n0 + h*64 + row;
            if (n < bRows) {
                float bv = (EPT == EPT_BIAS) ? bias[n] : 0.f;
                const float* srcr = sbuf + row*132;
                float* dstr = outF + ((size_t)zb * bRows + n) * LSEQ + tl0;
                int c0 = (tid & 3) * 4;
                #pragma unroll
                for (int q = 0; q < 8; q++) {
                    int col = c0 + q*16;
                    float4 v = *(const float4*)(srcr + col);
                    v.x += bv; v.y += bv; v.z += bv; v.w += bv;
                    *(float4*)(dstr + col) = v;
                }
            }
        }
    }
}

// ---------------- weight bf16 split ----------------
__global__ void wsplit_k(const float* __restrict__ w, __nv_bfloat16* __restrict__ h,
                         __nv_bfloat16* __restrict__ l, int n)
{
    int i = blockIdx.x * blockDim.x + threadIdx.x;
    if (i < n) { __nv_bfloat16 hh, ll; bf16split(w[i], hh, ll); h[i] = hh; l[i] = ll; }
}

// ---------------- transpose input0 -> token-major fp32 ----------------
__global__ void xposeF_k(const float* __restrict__ in, float* __restrict__ out)
{
    __shared__ float t[32][33];
    int b = blockIdx.z;
    int tok0 = blockIdx.x * 32, ch0 = blockIdx.y * 32;
    int lx = threadIdx.x & 31, ly = threadIdx.x >> 5;
    #pragma unroll
    for (int i = 0; i < 4; i++) {
        int ch = ch0 + ly + i*8;
        t[lx][ly + i*8] = in[((size_t)b*256 + ch)*LSEQ + tok0 + lx];
    }
    __syncthreads();
    #pragma unroll
    for (int i = 0; i < 4; i++) {
        int tok = tok0 + ly + i*8;
        out[((size_t)b*LSEQ + tok)*256 + ch0 + lx] = t[ly + i*8][lx];
    }
}

// ---------------- layernorm -> token-major bf16 hi/lo ----------------
__global__ void ln_k(const float* __restrict__ in0, const float* __restrict__ in1,
                     const float* __restrict__ w0, const float* __restrict__ b0,
                     const float* __restrict__ w1, const float* __restrict__ b1,
                     __nv_bfloat16* __restrict__ s0h, __nv_bfloat16* __restrict__ s0l,
                     __nv_bfloat16* __restrict__ s1h, __nv_bfloat16* __restrict__ s1l)
{
    int which = blockIdx.y;
    const float* in = which ? in1 : in0;
    const float* w  = which ? w1  : w0;
    const float* bb = which ? b1  : b0;
    __nv_bfloat16* oh = which ? s1h : s0h;
    __nv_bfloat16* ol = which ? s1l : s0l;
    int idx = blockIdx.x * blockDim.x + threadIdx.x;
    int b = idx >> 12, l = idx & (LSEQ-1);
    const float* p = in + (size_t)b*DIMC*LSEQ + l;
    float s = 0.f, s2 = 0.f;
    #pragma unroll 8
    for (int c = 0; c < DIMC; c++) { float v = p[(size_t)c*LSEQ]; s += v; s2 += v*v; }
    float mean = s * (1.f/DIMC);
    float var  = s2 * (1.f/DIMC) - mean*mean;
    float rstd = rsqrtf(var + EPS_F);
    size_t ob = (size_t)idx * 256;
    #pragma unroll 8
    for (int c = 0; c < DIMC; c++) {
        float v = (p[(size_t)c*LSEQ] - mean) * rstd * w[c] + bb[c];
        __nv_bfloat16 h, lo; bf16split(v, h, lo);
        oh[ob + c] = h; ol[ob + c] = lo;
    }
}

// ---------------- depthwise causal conv (K=4) + silu ----------------
__global__ void conv_silu_k(const float* __restrict__ x, const float* __restrict__ w,
                            const float* __restrict__ bias, float* __restrict__ xc, int rev)
{
    int t  = blockIdx.x * blockDim.x + threadIdx.x;
    int bd = blockIdx.y;
    int d  = bd & 255;
    const float* xp = x + (size_t)bd*LSEQ;
    float acc = bias[d];
    #pragma unroll
    for (int k = 0; k < 4; k++) {
        int s = t - 3 + k;
        if (s >= 0) {
            int ph = rev ? (LSEQ-1-s) : s;
            acc += w[d*4+k] * xp[ph];
        }
    }
    xc[(size_t)bd*LSEQ + t] = acc * sigmoidf_(acc);
}

// ---------------- fp32 SGEMM (xproj / dtproj) ----------------
enum { EP_NONE=0, EP_SPBIAS=1 };

template<int EP>
__global__ void __launch_bounds__(256) sgemm_k(
    const float* __restrict__ A, int lda, long long aStride,
    const float* __restrict__ B, int ldb, long long bStride,
    float* __restrict__ C, int ldc, long long cStride,
    int M, int Kdim, const float* __restrict__ bias)
{
    __shared__ float As[8][128];
    __shared__ float Bs[8][128];
    int zb = blockIdx.z;
    A += (size_t)zb * aStride;
    B += (size_t)zb * bStride;
    C += (size_t)zb * cStride;

    int m0 = blockIdx.y * 128;
    int n0 = blockIdx.x * 128;
    int tid = threadIdx.x;
    int ar  = tid >> 1, ac = (tid & 1) << 2;
    int brr = tid >> 5, bc = (tid & 31) << 2;
    int mt0 = (tid >> 4) << 2, nt0 = (tid & 15) << 2;

    unsigned long long acc[8][4];
    #pragma unroll
    for (int i = 0; i < 8; i++)
        #pragma unroll
        for (int j = 0; j < 4; j++) acc[i][j] = 0ull;

    for (int k0 = 0; k0 < Kdim; k0 += 8) {
        float4 a4 = make_float4(0.f,0.f,0.f,0.f);
        int arow = m0 + ar;
        if (arow < M) a4 = *(const float4*)(A + (size_t)arow*lda + (k0 + ac));
        As[ac+0][ar] = a4.x; As[ac+1][ar] = a4.y; As[ac+2][ar] = a4.z; As[ac+3][ar] = a4.w;
        float4 b4 = *(const float4*)(B + (size_t)(k0 + brr)*ldb + (n0 + bc));
        *(float4*)&Bs[brr][bc] = b4;
        __syncthreads();
        #pragma unroll
        for (int kk = 0; kk < 8; kk++) {
            float4 aL = *(const float4*)&As[kk][mt0];
            float4 aH = *(const float4*)&As[kk][mt0+64];
            float av[8] = {aL.x,aL.y,aL.z,aL.w,aH.x,aH.y,aH.z,aH.w};
            unsigned long long b2[4];
            const unsigned long long* bpL = (const unsigned long long*)&Bs[kk][nt0];
            const unsigned long long* bpH = (const unsigned long long*)&Bs[kk][nt0+64];
            b2[0] = bpL[0]; b2[1] = bpL[1]; b2[2] = bpH[0]; b2[3] = bpH[1];
            #pragma unroll
            for (int i = 0; i < 8; i++) {
                unsigned long long a2;
                asm("mov.b64 %0, {%1, %1};" : "=l"(a2) : "f"(av[i]));
                #pragma unroll
                for (int j = 0; j < 4; j++)
                    asm("fma.rn.f32x2 %0, %1, %2, %0;" : "+l"(acc[i][j]) : "l"(a2), "l"(b2[j]));
            }
        }
        __syncthreads();
    }

    #pragma unroll
    for (int i = 0; i < 8; i++) {
        int m = m0 + ((i < 4) ? (mt0 + i) : (64 + mt0 + i - 4));
        if (m >= M) continue;
        float bv = (EP == EP_SPBIAS) ? bias[m] : 0.f;
        #pragma unroll
        for (int j = 0; j < 4; j++) {
            int n = n0 + ((j < 2) ? (nt0 + 2*j) : (64 + nt0 + 2*(j-2)));
            float2 v;
            asm("mov.b64 {%0, %1}, %2;" : "=f"(v.x), "=f"(v.y) : "l"(acc[i][j]));
            if (EP == EP_SPBIAS) { v.x = softplusf_(v.x + bv); v.y = softplusf_(v.y + bv); }
            *(float2*)(C + (size_t)m*ldc + n) = v;
        }
    }
}

// ---------------- chunked selective scan ----------------
__global__ void __launch_bounds__(256) scanA_k(
    const float* __restrict__ dt, const float* __restrict__ xc,
    const float* __restrict__ dbl, const float* __restrict__ A_log,
    float* __restrict__ P, float* __restrict__ S)
{
    __shared__ float sdt[32][65], sx[32][65], sB[8][65];
    int chunk = blockIdx.x, b = blockIdx.y, d0 = blockIdx.z * 32;
    int tid = threadIdx.x;
    size_t base = ((size_t)(b*DIMC + d0))*LSEQ + chunk*64;
    for (int i = tid; i < 2048; i += 256) {
        int r = i >> 6, c = i & 63;
        sdt[r][c] = dt[base + (size_t)r*LSEQ + c];
        sx [r][c] = xc[base + (size_t)r*LSEQ + c];
    }
    size_t bbase = ((size_t)(b*32 + 16))*LSEQ + chunk*64;
    for (int i = tid; i < 512; i += 256) {
        int r = i >> 6, c = i & 63;
        sB[r][c] = dbl[bbase + (size_t)r*LSEQ + c];
    }
    __syncthreads();
    int dl = tid >> 3, n = tid & 7;
    float Aa = -__expf(A_log[(d0+dl)*8 + n]);
    float Pv = 1.f, Sv = 0.f;
    #pragma unroll 8
    for (int t = 0; t < 64; t++) {
        float dtv = sdt[dl][t];
        float dA  = __expf(dtv * Aa);
        Sv = Sv*dA + dtv * sx[dl][t] * sB[n][t];
        Pv *= dA;
    }
    size_t o = (((size_t)chunk*BATCH + b)*DIMC + d0+dl)*8 + n;
    P[o] = Pv; S[o] = Sv;
}

__global__ void scanB_k(const float* __restrict__ P, const float* __restrict__ S,
                        float* __restrict__ Hi)
{
    int idx = blockIdx.x * blockDim.x + threadIdx.x;
    float h = 0.f;
    for (int c = 0; c < 64; c++) {
        size_t o = (size_t)c*4096 + idx;
        Hi[o] = h;
        h = h * P[o] + S[o];
    }
}

__global__ void __launch_bounds__(256) scanC_k(
    const float* __restrict__ dt, const float* __restrict__ xc,
    const float* __restrict__ dbl, const float* __restrict__ A_log,
    const float* __restrict__ Hi, const float* __restrict__ Dp,
    const float* __restrict__ z, float* __restrict__ y, int rev)
{
    __shared__ float sdt[32][65], sx[32][65], sB[8][65], sC[8][65];
    __shared__ float sy[32][64];
    int chunk = blockIdx.x, b = blockIdx.y, d0 = blockIdx.z * 32;
    int tid = threadIdx.x;
    size_t base = ((size_t)(b*DIMC + d0))*LSEQ + chunk*64;
    for (int i = tid; i < 2048; i += 256) {
        int r = i >> 6, c = i & 63;
        sdt[r][c] = dt[base + (size_t)r*LSEQ + c];
        sx [r][c] = xc[base + (size_t)r*LSEQ + c];
    }
    size_t bbase = ((size_t)(b*32 + 16))*LSEQ + chunk*64;
    size_t cbase = ((size_t)(b*32 + 24))*LSEQ + chunk*64;
    for (int i = tid; i < 512; i += 256) {
        int r = i >> 6, c = i & 63;
        sB[r][c] = dbl[bbase + (size_t)r*LSEQ + c];
        sC[r][c] = dbl[cbase + (size_t)r*LSEQ + c];
    }
    __syncthreads();
    int dl = tid >> 3, n = tid & 7;
    float Aa = -__expf(A_log[(d0+dl)*8 + n]);
    float h = Hi[(((size_t)chunk*BATCH + b)*DIMC + d0+dl)*8 + n];
    for (int t = 0; t < 64; t++) {
        float dtv = sdt[dl][t];
        float dA  = __expf(dtv * Aa);
        h = h*dA + dtv * sx[dl][t] * sB[n][t];
        float yv = h * sC[n][t];
        yv += __shfl_down_sync(0xffffffffu, yv, 4);
        yv += __shfl_down_sync(0xffffffffu, yv, 2);
        yv += __shfl_down_sync(0xffffffffu, yv, 1);
        if (n == 0) sy[dl][t] = yv;
    }
    __syncthreads();
    for (int i = tid; i < 2048; i += 256) {
        int r = i >> 6, c = i & 63;
        int tl = chunk*64 + c;
        int lp = rev ? (LSEQ-1-tl) : tl;
        size_t gi = ((size_t)(b*DIMC + d0 + r))*LSEQ + lp;
        float v = sy[r][c] + sx[r][c]*Dp[d0+r];
        float zz = z[gi];
        y[gi] = v * zz * sigmoidf_(zz);
    }
}

// ---------------- rmsnorm for 3 heads -> token-major bf16 hi/lo ----------------
__global__ void rms3_k(const float* __restrict__ yf, const float* __restrict__ yb,
                       const float* __restrict__ w,
                       __nv_bfloat16* __restrict__ ynh, __nv_bfloat16* __restrict__ ynl)
{
    int idx = blockIdx.x * blockDim.x + threadIdx.x;
    int b = idx >> 12, l = idx & (LSEQ-1);
    size_t base = (size_t)b*DIMC*LSEQ + l;
    float sa = 0.f, sf = 0.f, sb = 0.f;
    #pragma unroll 8
    for (int d = 0; d < DIMC; d++) {
        float vf = yf[base + (size_t)d*LSEQ];
        float vb = yb[base + (size_t)d*LSEQ];
        float va = 0.5f*(vf+vb);
        sa += va*va; sf += vf*vf; sb += vb*vb;
    }
    float ra = rsqrtf(sa*(1.f/DIMC) + EPS_F);
    float rf = rsqrtf(sf*(1.f/DIMC) + EPS_F);
    float rb = rsqrtf(sb*(1.f/DIMC) + EPS_F);
    size_t r0 = ((size_t)(0*2 + b)*LSEQ + l) * 256;
    size_t r1 = ((size_t)(1*2 + b)*LSEQ + l) * 256;
    size_t r2 = ((size_t)(2*2 + b)*LSEQ + l) * 256;
    #pragma unroll 8
    for (int d = 0; d < DIMC; d++) {
        float vf = yf[base + (size_t)d*LSEQ];
        float vb = yb[base + (size_t)d*LSEQ];
        float va = 0.5f*(vf+vb);
        float ww = w[d];
        __nv_bfloat16 h, lo;
        bf16split(va*ra*ww, h, lo); ynh[r0+d] = h; ynl[r0+d] = lo;
        bf16split(vf*rf*ww, h, lo); ynh[r1+d] = h; ynl[r1+d] = lo;
        bf16split(vb*rb*ww, h, lo); ynh[r2+d] = h; ynl[r2+d] = lo;
    }
}

// ---------------- launch ----------------
extern "C" void kernel_launch(void* const* d_in, const int* in_sizes, int n_in,
                              void* d_out, int out_size)
{
    (void)in_sizes; (void)n_in; (void)out_size;
    const float* input0      = (const float*)d_in[0];
    const float* input1      = (const float*)d_in[1];
    const float* norm0_w     = (const float*)d_in[2];
    const float* norm0_b     = (const float*)d_in[3];
    const float* norm1_w     = (const float*)d_in[4];
    const float* norm1_b     = (const float*)d_in[5];
    const float* in_proj_w   = (const float*)d_in[6];
    const float* in_projz_w  = (const float*)d_in[7];
    const float* conv1d_w    = (const float*)d_in[8];
    const float* conv1d_bias = (const float*)d_in[9];
    const float* conv1db_w   = (const float*)d_in[10];
    const float* conv1db_bias= (const float*)d_in[11];
    const float* xproj_w     = (const float*)d_in[12];
    const float* xprojb_w    = (const float*)d_in[13];
    const float* dtproj_w    = (const float*)d_in[14];
    const float* dtproj_bias = (const float*)d_in[15];
    const float* dtprojb_w   = (const float*)d_in[16];
    const float* dtprojb_bias= (const float*)d_in[17];
    const float* A_log       = (const float*)d_in[18];
    const float* Ab_log      = (const float*)d_in[19];
    const float* D_p         = (const float*)d_in[20];
    const float* D_b         = (const float*)d_in[21];
    const float* rms_w       = (const float*)d_in[22];
    const float* out_proj_w  = (const float*)d_in[23];
    const float* conv3d_w    = (const float*)d_in[24];
    const float* conv3d_bias = (const float*)d_in[25];
    float* out = (float*)d_out;

    float *x_, *z_, *xc_, *dbl_, *dt_, *P_, *S_, *Hi_, *y_, *skipT;
    __nv_bfloat16 *s0h,*s0l,*s1h,*s1l,*ynh,*ynl,*oh,*ol;
    __nv_bfloat16 *wip_h,*wip_l,*wiz_h,*wiz_l,*wop_h,*wop_l,*wc3_h,*wc3_l;
    cudaGetSymbolAddress((void**)&x_,   g_x);
    cudaGetSymbolAddress((void**)&z_,   g_z);
    cudaGetSymbolAddress((void**)&xc_,  g_xc);
    cudaGetSymbolAddress((void**)&dbl_, g_dbl);
    cudaGetSymbolAddress((void**)&dt_,  g_dt);
    cudaGetSymbolAddress((void**)&P_,   g_P);
    cudaGetSymbolAddress((void**)&S_,   g_S);
    cudaGetSymbolAddress((void**)&Hi_,  g_Hi);
    cudaGetSymbolAddress((void**)&y_,   g_y);
    cudaGetSymbolAddress((void**)&skipT,g_skipT);
    cudaGetSymbolAddress((void**)&s0h,  g_s0h);
    cudaGetSymbolAddress((void**)&s0l,  g_s0l);
    cudaGetSymbolAddress((void**)&s1h,  g_s1h);
    cudaGetSymbolAddress((void**)&s1l,  g_s1l);
    cudaGetSymbolAddress((void**)&ynh,  g_ynh);
    cudaGetSymbolAddress((void**)&ynl,  g_ynl);
    cudaGetSymbolAddress((void**)&oh,   g_oh);
    cudaGetSymbolAddress((void**)&ol,   g_ol);
    cudaGetSymbolAddress((void**)&wip_h, g_wip_h); cudaGetSymbolAddress((void**)&wip_l, g_wip_l);
    cudaGetSymbolAddress((void**)&wiz_h, g_wiz_h); cudaGetSymbolAddress((void**)&wiz_l, g_wiz_l);
    cudaGetSymbolAddress((void**)&wop_h, g_wop_h); cudaGetSymbolAddress((void**)&wop_l, g_wop_l);
    cudaGetSymbolAddress((void**)&wc3_h, g_wc3_h); cudaGetSymbolAddress((void**)&wc3_l, g_wc3_l);

    const int TCSMEM = 4 * TILE_B;   // 73728
    cudaFuncSetAttribute(tcgemm_k<EPT_XPOSE>, cudaFuncAttributeMaxDynamicSharedMemorySize, TCSMEM);
    cudaFuncSetAttribute(tcgemm_k<EPT_SKIP>,  cudaFuncAttributeMaxDynamicSharedMemorySize, TCSMEM);
    cudaFuncSetAttribute(tcgemm_k<EPT_BIAS>,  cudaFuncAttributeMaxDynamicSharedMemorySize, TCSMEM);

    const long long SB  = (long long)DIMC*LSEQ;
    const long long SB32= (long long)32*LSEQ;
    const int SCN = 64*BATCH*DIMC*8;

    // 0) weight splits + skip transpose
    wsplit_k<<<256, 256>>>(in_proj_w,  wip_h, wip_l, 65536);
    wsplit_k<<<256, 256>>>(in_projz_w, wiz_h, wiz_l, 65536);
    wsplit_k<<<256, 256>>>(out_proj_w, wop_h, wop_l, 65536);
    wsplit_k<<<1200, 256>>>(conv3d_w,  wc3_h, wc3_l, 307200);
    xposeF_k<<<dim3(128,8,2), 256>>>(input0, skipT);

    // 1) layernorms -> token-major bf16 hi/lo
    ln_k<<<dim3(32,2), 256>>>(input0, input1, norm0_w, norm0_b, norm1_w, norm1_b,
                              s0h, s0l, s1h, s1l);

    // 2) in_proj / in_projz on tensor cores -> channel-major fp32
    tcgemm_k<EPT_XPOSE><<<dim3(2,32,2), 256, TCSMEM>>>(s0h, s0l, wip_h, wip_l, 256,
                                                       x_, nullptr, nullptr, nullptr, nullptr);
    tcgemm_k<EPT_XPOSE><<<dim3(2,32,2), 256, TCSMEM>>>(s1h, s1l, wiz_h, wiz_l, 256,
                                                       z_, nullptr, nullptr, nullptr, nullptr);

    for (int dir = 0; dir < 2; dir++) {
        float* xcD  = xc_  + (size_t)dir*BATCH*DIMC*LSEQ;
        float* dblD = dbl_ + (size_t)dir*BATCH*32*LSEQ;
        float* dtD  = dt_  + (size_t)dir*BATCH*DIMC*LSEQ;
        float* PD   = P_   + (size_t)dir*SCN;
        float* SD   = S_   + (size_t)dir*SCN;
        float* HiD  = Hi_  + (size_t)dir*SCN;
        float* yD   = y_   + (size_t)dir*BATCH*DIMC*LSEQ;
        const float* cw = dir ? conv1db_w    : conv1d_w;
        const float* cb = dir ? conv1db_bias : conv1d_bias;
        const float* xw = dir ? xprojb_w     : xproj_w;
        const float* dw = dir ? dtprojb_w    : dtproj_w;
        const float* db = dir ? dtprojb_bias : dtproj_bias;
        const float* al = dir ? Ab_log       : A_log;
        const float* Dd = dir ? D_b          : D_p;

        conv_silu_k<<<dim3(16,512), 256>>>(x_, cw, cb, xcD, dir);
        sgemm_k<EP_NONE><<<dim3(32,1,2), 256>>>(xw, 256, 0, xcD, LSEQ, SB,
                                                dblD, LSEQ, SB32, 32, 256, nullptr);
        sgemm_k<EP_SPBIAS><<<dim3(32,2,2), 256>>>(dw, 16, 0, dblD, LSEQ, SB32,
                                                  dtD, LSEQ, SB, 256, 16, db);
        scanA_k<<<dim3(64,2,8), 256>>>(dtD, xcD, dblD, al, PD, SD);
        scanB_k<<<16, 256>>>(PD, SD, HiD);
        scanC_k<<<dim3(64,2,8), 256>>>(dtD, xcD, dblD, al, HiD, Dd, z_, yD, dir);
    }

    // 7) rmsnorm 3 heads -> token-major bf16 hi/lo
    rms3_k<<<32, 256>>>(y_, y_ + (size_t)BATCH*DIMC*LSEQ, rms_w, ynh, ynl);

    // 8) out_proj (+skip) on tensor cores -> o hi/lo (token-major bf16)
    tcgemm_k<EPT_SKIP><<<dim3(2,32,6), 256, TCSMEM>>>(ynh, ynl, wop_h, wop_l, 256,
                                                      nullptr, nullptr, skipT, oh, ol);

    // 9) conv3d on tensor cores (+bias) -> final output (channel-major fp32)
    tcgemm_k<EPT_BIAS><<<dim3(10,32,6), 256, TCSMEM>>>(oh, ol, wc3_h, wc3_l, 1200,
                                                       out, conv3d_bias, nullptr, nullptr, nullptr);
}

// round 9
// speedup vs baseline: 1.1758x; 1.1758x over previous
#include <cuda_runtime.h>
#include <cuda_bf16.h>
#include <cstdint>
#include <math.h>

#define LSEQ 4096
#define BATCH 2
#define DIMC 256
#define EPS_F 1e-5f

// ---------------- scratch (device globals) ----------------
__device__ float g_x   [BATCH*DIMC*LSEQ];
__device__ float g_z   [BATCH*DIMC*LSEQ];
__device__ float g_xc  [2][BATCH*DIMC*LSEQ];
__device__ float g_dbl [2][BATCH*32*LSEQ];
__device__ float g_dt  [2][BATCH*DIMC*LSEQ];
__device__ float g_P   [2][64*BATCH*DIMC*8];
__device__ float g_S   [2][64*BATCH*DIMC*8];
__device__ float g_Hi  [2][64*BATCH*DIMC*8];
__device__ float g_y   [2][BATCH*DIMC*LSEQ];
__device__ float g_skipT[BATCH*LSEQ*DIMC];   // input0 transposed to token-major fp32

// bf16 split activations / weights (token-major, K=256 contiguous)
__device__ __nv_bfloat16 g_s0h[BATCH*LSEQ*DIMC], g_s0l[BATCH*LSEQ*DIMC];
__device__ __nv_bfloat16 g_s1h[BATCH*LSEQ*DIMC], g_s1l[BATCH*LSEQ*DIMC];
__device__ __nv_bfloat16 g_ynh[6*LSEQ*DIMC],     g_ynl[6*LSEQ*DIMC];
__device__ __nv_bfloat16 g_oh [6*LSEQ*DIMC],     g_ol [6*LSEQ*DIMC];
__device__ __nv_bfloat16 g_wip_h[DIMC*DIMC], g_wip_l[DIMC*DIMC];
__device__ __nv_bfloat16 g_wiz_h[DIMC*DIMC], g_wiz_l[DIMC*DIMC];
__device__ __nv_bfloat16 g_wop_h[DIMC*DIMC], g_wop_l[DIMC*DIMC];
__device__ __nv_bfloat16 g_wc3_h[1200*DIMC], g_wc3_l[1200*DIMC];

__device__ __forceinline__ float sigmoidf_(float x){ return 1.f/(1.f+__expf(-x)); }
__device__ __forceinline__ float softplusf_(float x){ return x>20.f ? x : log1pf(__expf(x)); }

__device__ __forceinline__ void bf16split(float v, __nv_bfloat16& h, __nv_bfloat16& l) {
    h = __float2bfloat16(v);
    l = __float2bfloat16(v - __bfloat162float(h));
}

__device__ __forceinline__ uint32_t smem_u32(const void* p) {
    uint32_t a;
    asm("{ .reg .u64 t; cvta.to.shared.u64 t, %1; cvt.u32.u64 %0, t; }" : "=r"(a) : "l"(p));
    return a;
}
__device__ __forceinline__ void ldmx4(uint32_t* r, uint32_t addr) {
    asm volatile("ldmatrix.sync.aligned.m8n8.x4.shared.b16 {%0,%1,%2,%3}, [%4];"
        : "=r"(r[0]),"=r"(r[1]),"=r"(r[2]),"=r"(r[3]) : "r"(addr));
}
__device__ __forceinline__ void mma16816(float* d, const uint32_t* a, uint32_t b0, uint32_t b1) {
    asm volatile("mma.sync.aligned.m16n8k16.row.col.f32.bf16.bf16.f32 "
        "{%0,%1,%2,%3}, {%4,%5,%6,%7}, {%8,%9}, {%0,%1,%2,%3};"
        : "+f"(d[0]),"+f"(d[1]),"+f"(d[2]),"+f"(d[3])
        : "r"(a[0]),"r"(a[1]),"r"(a[2]),"r"(a[3]), "r"(b0),"r"(b1));
}

// ---------------- split-bf16 GEMM on tensor cores via mma.sync ----------------
// D[128 tok, 128 ch] = A[tok,256] * W[ch,256]^T, A/W pre-split hi/lo bf16 (3 passes).
// SMEM: 4 tiles [128][72] bf16 (K-chunk 64, +8 pad). 8 warps: (mw 0..3) x (nw 0..1),
// each warp 32(M) x 64(N) via m16n8k16. NOTE: no min-blocks clause -> no 128-reg
// cap -> no spills in the mma loop (R8 regression root cause).
#define EPT_XPOSE 0
#define EPT_SKIP  1
#define EPT_BIAS  2
#define TILE_B 18432

template<int EPT>
__global__ void __launch_bounds__(256) tcgemm_k(
    const __nv_bfloat16* __restrict__ Ah, const __nv_bfloat16* __restrict__ Al,
    const __nv_bfloat16* __restrict__ Bh, const __nv_bfloat16* __restrict__ Bl,
    int bRows,
    float* __restrict__ outF, const float* __restrict__ bias,
    const float* __restrict__ skipT,
    __nv_bfloat16* __restrict__ Oh, __nv_bfloat16* __restrict__ Ol)
{
    extern __shared__ char smem[];
    const int tid = threadIdx.x, lane = tid & 31, warp = tid >> 5;
    const int mw = warp & 3, nw = warp >> 2;
    const int n0 = blockIdx.x * 128, tl0 = blockIdx.y * 128, zb = blockIdx.z;
    const long long t0 = (long long)zb * LSEQ + tl0;

    float acc[2][8][4];
    #pragma unroll
    for (int i = 0; i < 2; i++)
        #pragma unroll
        for (int j = 0; j < 8; j++)
            #pragma unroll
            for (int c = 0; c < 4; c++) acc[i][j][c] = 0.f;

    const uint32_t sbase = smem_u32(smem);
    const int a_row  = (lane & 7) + ((lane >> 3) & 1) * 8;
    const int a_kadd = (lane >> 4) * 8;
    const int b_row  = (lane & 7) + (lane >> 4) * 8;
    const int b_kadd = ((lane >> 3) & 1) * 8;
    const uint32_t aoffH = sbase + 0      + (uint32_t)((mw*32 + a_row)*72 + a_kadd) * 2;
    const uint32_t aoffL = aoffH + TILE_B;
    const uint32_t boffH = sbase + 2*TILE_B + (uint32_t)((nw*64 + b_row)*72 + b_kadd) * 2;
    const uint32_t boffL = boffH + TILE_B;

    const int lrow = tid >> 3, lc8 = (tid & 7) * 8;

    for (int kc = 0; kc < 4; kc++) {
        if (kc) __syncthreads();
        #pragma unroll
        for (int it = 0; it < 4; it++) {
            int row = lrow + it * 32;
            uint32_t so = (uint32_t)(row * 72 + lc8) * 2;
            *(uint4*)(smem + so)          = *(const uint4*)(Ah + (t0+row)*256 + kc*64 + lc8);
            *(uint4*)(smem + TILE_B + so) = *(const uint4*)(Al + (t0+row)*256 + kc*64 + lc8);
            uint4 vh = make_uint4(0u,0u,0u,0u), vl = make_uint4(0u,0u,0u,0u);
            if (n0 + row < bRows) {
                vh = *(const uint4*)(Bh + (size_t)(n0+row)*256 + kc*64 + lc8);
                vl = *(const uint4*)(Bl + (size_t)(n0+row)*256 + kc*64 + lc8);
            }
            *(uint4*)(smem + 2*TILE_B + so) = vh;
            *(uint4*)(smem + 3*TILE_B + so) = vl;
        }
        __syncthreads();

        #pragma unroll
        for (int ks = 0; ks < 4; ks++) {
            const uint32_t k2 = (uint32_t)(ks * 16) * 2;
            uint32_t aH[2][4], aL[2][4];
            #pragma unroll
            for (int i = 0; i < 2; i++) {
                ldmx4(aH[i], aoffH + i*16*144 + k2);
                ldmx4(aL[i], aoffL + i*16*144 + k2);
            }
            #pragma unroll
            for (int half = 0; half < 2; half++) {
                uint32_t bH[2][4], bL[2][4];
                #pragma unroll
                for (int gg = 0; gg < 2; gg++) {
                    int g = half*2 + gg;
                    ldmx4(bH[gg], boffH + g*16*144 + k2);
                    ldmx4(bL[gg], boffL + g*16*144 + k2);
                }
                #pragma unroll
                for (int i = 0; i < 2; i++)
                    #pragma unroll
                    for (int gg = 0; gg < 2; gg++)
                        #pragma unroll
                        for (int p = 0; p < 2; p++) {
                            int j8 = (half*2 + gg)*2 + p;
                            mma16816(acc[i][j8], aH[i], bH[gg][2*p], bH[gg][2*p+1]);
                            mma16816(acc[i][j8], aH[i], bL[gg][2*p], bL[gg][2*p+1]);
                            mma16816(acc[i][j8], aL[i], bH[gg][2*p], bH[gg][2*p+1]);
                        }
            }
        }
    }

    if (EPT == EPT_SKIP) {
        #pragma unroll
        for (int i = 0; i < 2; i++)
            #pragma unroll
            for (int rr = 0; rr < 2; rr++) {
                int tok = tl0 + mw*32 + i*16 + (lane >> 2) + rr*8;
                size_t orow = ((size_t)zb * LSEQ + tok) * 256;
                size_t srow = ((size_t)(zb & 1) * LSEQ + tok) * 256;
                #pragma unroll
                for (int j8 = 0; j8 < 8; j8++) {
                    int n = n0 + nw*64 + j8*8 + 2*(lane & 3);
                    float2 sk = *(const float2*)(skipT + srow + n);
                    float v0 = acc[i][j8][rr*2+0] + sk.x;
                    float v1 = acc[i][j8][rr*2+1] + sk.y;
                    __nv_bfloat16 h0,l0,h1,l1;
                    bf16split(v0,h0,l0); bf16split(v1,h1,l1);
                    __nv_bfloat162 ph; ph.x = h0; ph.y = h1;
                    __nv_bfloat162 pl; pl.x = l0; pl.y = l1;
                    *(__nv_bfloat162*)(Oh + orow + n) = ph;
                    *(__nv_bfloat162*)(Ol + orow + n) = pl;
                }
            }
    } else {
        float* sbuf = (float*)smem;
        #pragma unroll 1
        for (int h = 0; h < 2; h++) {
            __syncthreads();
            if (nw == h) {
                #pragma unroll
                for (int i = 0; i < 2; i++)
                    #pragma unroll
                    for (int j8 = 0; j8 < 8; j8++)
                        #pragma unroll
                        for (int rr = 0; rr < 2; rr++) {
                            int tok = mw*32 + i*16 + (lane >> 2) + rr*8;
                            int nl = j8*8 + 2*(lane & 3);
                            sbuf[nl*132 + tok]     = acc[i][j8][rr*2+0];
                            sbuf[(nl+1)*132 + tok] = acc[i][j8][rr*2+1];
                        }
            }
            __syncthreads();
            int row = tid >> 2;
            int n = n0 + h*64 + row;
            if (n < bRows) {
                float bv = (EPT == EPT_BIAS) ? bias[n] : 0.f;
                const float* srcr = sbuf + row*132;
                float* dstr = outF + ((size_t)zb * bRows + n) * LSEQ + tl0;
                int c0 = (tid & 3) * 4;
                #pragma unroll
                for (int q = 0; q < 8; q++) {
                    int col = c0 + q*16;
                    float4 v = *(const float4*)(srcr + col);
                    v.x += bv; v.y += bv; v.z += bv; v.w += bv;
                    *(float4*)(dstr + col) = v;
                }
            }
        }
    }
}

// ---------------- weight bf16 split ----------------
__global__ void wsplit_k(const float* __restrict__ w, __nv_bfloat16* __restrict__ h,
                         __nv_bfloat16* __restrict__ l, int n)
{
    int i = blockIdx.x * blockDim.x + threadIdx.x;
    if (i < n) { __nv_bfloat16 hh, ll; bf16split(w[i], hh, ll); h[i] = hh; l[i] = ll; }
}

// ---------------- transpose input0 -> token-major fp32 ----------------
__global__ void xposeF_k(const float* __restrict__ in, float* __restrict__ out)
{
    __shared__ float t[32][33];
    int b = blockIdx.z;
    int tok0 = blockIdx.x * 32, ch0 = blockIdx.y * 32;
    int lx = threadIdx.x & 31, ly = threadIdx.x >> 5;
    #pragma unroll
    for (int i = 0; i < 4; i++) {
        int ch = ch0 + ly + i*8;
        t[lx][ly + i*8] = in[((size_t)b*256 + ch)*LSEQ + tok0 + lx];
    }
    __syncthreads();
    #pragma unroll
    for (int i = 0; i < 4; i++) {
        int tok = tok0 + ly + i*8;
        out[((size_t)b*LSEQ + tok)*256 + ch0 + lx] = t[ly + i*8][lx];
    }
}

// ---------------- layernorm -> token-major bf16 hi/lo (vectorized 16B stores) ----------------
__global__ void ln_k(const float* __restrict__ in0, const float* __restrict__ in1,
                     const float* __restrict__ w0, const float* __restrict__ b0,
                     const float* __restrict__ w1, const float* __restrict__ b1,
                     __nv_bfloat16* __restrict__ s0h, __nv_bfloat16* __restrict__ s0l,
                     __nv_bfloat16* __restrict__ s1h, __nv_bfloat16* __restrict__ s1l)
{
    int which = blockIdx.y;
    const float* in = which ? in1 : in0;
    const float* w  = which ? w1  : w0;
    const float* bb = which ? b1  : b0;
    __nv_bfloat16* oh = which ? s1h : s0h;
    __nv_bfloat16* ol = which ? s1l : s0l;
    int idx = blockIdx.x * blockDim.x + threadIdx.x;
    int b = idx >> 12, l = idx & (LSEQ-1);
    const float* p = in + (size_t)b*DIMC*LSEQ + l;
    float s = 0.f, s2 = 0.f;
    #pragma unroll 8
    for (int c = 0; c < DIMC; c++) { float v = p[(size_t)c*LSEQ]; s += v; s2 += v*v; }
    float mean = s * (1.f/DIMC);
    float var  = s2 * (1.f/DIMC) - mean*mean;
    float rstd = rsqrtf(var + EPS_F);
    size_t ob = (size_t)idx * 256;
    for (int c0 = 0; c0 < DIMC; c0 += 8) {
        __align__(16) __nv_bfloat16 hh[8], ll[8];
        #pragma unroll
        for (int j = 0; j < 8; j++) {
            float v = (p[(size_t)(c0+j)*LSEQ] - mean) * rstd * w[c0+j] + bb[c0+j];
            bf16split(v, hh[j], ll[j]);
        }
        *(uint4*)(oh + ob + c0) = *(uint4*)hh;
        *(uint4*)(ol + ob + c0) = *(uint4*)ll;
    }
}

// ---------------- depthwise causal conv (K=4) + silu ----------------
__global__ void conv_silu_k(const float* __restrict__ x, const float* __restrict__ w,
                            const float* __restrict__ bias, float* __restrict__ xc, int rev)
{
    int t  = blockIdx.x * blockDim.x + threadIdx.x;
    int bd = blockIdx.y;
    int d  = bd & 255;
    const float* xp = x + (size_t)bd*LSEQ;
    float acc = bias[d];
    #pragma unroll
    for (int k = 0; k < 4; k++) {
        int s = t - 3 + k;
        if (s >= 0) {
            int ph = rev ? (LSEQ-1-s) : s;
            acc += w[d*4+k] * xp[ph];
        }
    }
    xc[(size_t)bd*LSEQ + t] = acc * sigmoidf_(acc);
}

// ---------------- fp32 SGEMM (xproj / dtproj) ----------------
enum { EP_NONE=0, EP_SPBIAS=1 };

template<int EP>
__global__ void __launch_bounds__(256) sgemm_k(
    const float* __restrict__ A, int lda, long long aStride,
    const float* __restrict__ B, int ldb, long long bStride,
    float* __restrict__ C, int ldc, long long cStride,
    int M, int Kdim, const float* __restrict__ bias)
{
    __shared__ float As[8][128];
    __shared__ float Bs[8][128];
    int zb = blockIdx.z;
    A += (size_t)zb * aStride;
    B += (size_t)zb * bStride;
    C += (size_t)zb * cStride;

    int m0 = blockIdx.y * 128;
    int n0 = blockIdx.x * 128;
    int tid = threadIdx.x;
    int ar  = tid >> 1, ac = (tid & 1) << 2;
    int brr = tid >> 5, bc = (tid & 31) << 2;
    int mt0 = (tid >> 4) << 2, nt0 = (tid & 15) << 2;

    unsigned long long acc[8][4];
    #pragma unroll
    for (int i = 0; i < 8; i++)
        #pragma unroll
        for (int j = 0; j < 4; j++) acc[i][j] = 0ull;

    for (int k0 = 0; k0 < Kdim; k0 += 8) {
        float4 a4 = make_float4(0.f,0.f,0.f,0.f);
        int arow = m0 + ar;
        if (arow < M) a4 = *(const float4*)(A + (size_t)arow*lda + (k0 + ac));
        As[ac+0][ar] = a4.x; As[ac+1][ar] = a4.y; As[ac+2][ar] = a4.z; As[ac+3][ar] = a4.w;
        float4 b4 = *(const float4*)(B + (size_t)(k0 + brr)*ldb + (n0 + bc));
        *(float4*)&Bs[brr][bc] = b4;
        __syncthreads();
        #pragma unroll
        for (int kk = 0; kk < 8; kk++) {
            float4 aL = *(const float4*)&As[kk][mt0];
            float4 aH = *(const float4*)&As[kk][mt0+64];
            float av[8] = {aL.x,aL.y,aL.z,aL.w,aH.x,aH.y,aH.z,aH.w};
            unsigned long long b2[4];
            const unsigned long long* bpL = (const unsigned long long*)&Bs[kk][nt0];
            const unsigned long long* bpH = (const unsigned long long*)&Bs[kk][nt0+64];
            b2[0] = bpL[0]; b2[1] = bpL[1]; b2[2] = bpH[0]; b2[3] = bpH[1];
            #pragma unroll
            for (int i = 0; i < 8; i++) {
                unsigned long long a2;
                asm("mov.b64 %0, {%1, %1};" : "=l"(a2) : "f"(av[i]));
                #pragma unroll
                for (int j = 0; j < 4; j++)
                    asm("fma.rn.f32x2 %0, %1, %2, %0;" : "+l"(acc[i][j]) : "l"(a2), "l"(b2[j]));
            }
        }
        __syncthreads();
    }

    #pragma unroll
    for (int i = 0; i < 8; i++) {
        int m = m0 + ((i < 4) ? (mt0 + i) : (64 + mt0 + i - 4));
        if (m >= M) continue;
        float bv = (EP == EP_SPBIAS) ? bias[m] : 0.f;
        #pragma unroll
        for (int j = 0; j < 4; j++) {
            int n = n0 + ((j < 2) ? (nt0 + 2*j) : (64 + nt0 + 2*(j-2)));
            float2 v;
            asm("mov.b64 {%0, %1}, %2;" : "=f"(v.x), "=f"(v.y) : "l"(acc[i][j]));
            if (EP == EP_SPBIAS) { v.x = softplusf_(v.x + bv); v.y = softplusf_(v.y + bv); }
            *(float2*)(C + (size_t)m*ldc + n) = v;
        }
    }
}

// ---------------- chunked selective scan ----------------
__global__ void __launch_bounds__(256) scanA_k(
    const float* __restrict__ dt, const float* __restrict__ xc,
    const float* __restrict__ dbl, const float* __restrict__ A_log,
    float* __restrict__ P, float* __restrict__ S)
{
    __shared__ float sdt[32][65], sx[32][65], sB[8][65];
    int chunk = blockIdx.x, b = blockIdx.y, d0 = blockIdx.z * 32;
    int tid = threadIdx.x;
    size_t base = ((size_t)(b*DIMC + d0))*LSEQ + chunk*64;
    for (int i = tid; i < 2048; i += 256) {
        int r = i >> 6, c = i & 63;
        sdt[r][c] = dt[base + (size_t)r*LSEQ + c];
        sx [r][c] = xc[base + (size_t)r*LSEQ + c];
    }
    size_t bbase = ((size_t)(b*32 + 16))*LSEQ + chunk*64;
    for (int i = tid; i < 512; i += 256) {
        int r = i >> 6, c = i & 63;
        sB[r][c] = dbl[bbase + (size_t)r*LSEQ + c];
    }
    __syncthreads();
    int dl = tid >> 3, n = tid & 7;
    float Aa = -__expf(A_log[(d0+dl)*8 + n]);
    float Pv = 1.f, Sv = 0.f;
    #pragma unroll 8
    for (int t = 0; t < 64; t++) {
        float dtv = sdt[dl][t];
        float dA  = __expf(dtv * Aa);
        Sv = Sv*dA + dtv * sx[dl][t] * sB[n][t];
        Pv *= dA;
    }
    size_t o = (((size_t)chunk*BATCH + b)*DIMC + d0+dl)*8 + n;
    P[o] = Pv; S[o] = Sv;
}

__global__ void scanB_k(const float* __restrict__ P, const float* __restrict__ S,
                        float* __restrict__ Hi)
{
    int idx = blockIdx.x * blockDim.x + threadIdx.x;
    float h = 0.f;
    for (int c = 0; c < 64; c++) {
        size_t o = (size_t)c*4096 + idx;
        Hi[o] = h;
        h = h * P[o] + S[o];
    }
}

__global__ void __launch_bounds__(256) scanC_k(
    const float* __restrict__ dt, const float* __restrict__ xc,
    const float* __restrict__ dbl, const float* __restrict__ A_log,
    const float* __restrict__ Hi, const float* __restrict__ Dp,
    const float* __restrict__ z, float* __restrict__ y, int rev)
{
    __shared__ float sdt[32][65], sx[32][65], sB[8][65], sC[8][65];
    __shared__ float sy[32][64];
    int chunk = blockIdx.x, b = blockIdx.y, d0 = blockIdx.z * 32;
    int tid = threadIdx.x;
    size_t base = ((size_t)(b*DIMC + d0))*LSEQ + chunk*64;
    for (int i = tid; i < 2048; i += 256) {
        int r = i >> 6, c = i & 63;
        sdt[r][c] = dt[base + (size_t)r*LSEQ + c];
        sx [r][c] = xc[base + (size_t)r*LSEQ + c];
    }
    size_t bbase = ((size_t)(b*32 + 16))*LSEQ + chunk*64;
    size_t cbase = ((size_t)(b*32 + 24))*LSEQ + chunk*64;
    for (int i = tid; i < 512; i += 256) {
        int r = i >> 6, c = i & 63;
        sB[r][c] = dbl[bbase + (size_t)r*LSEQ + c];
        sC[r][c] = dbl[cbase + (size_t)r*LSEQ + c];
    }
    __syncthreads();
    int dl = tid >> 3, n = tid & 7;
    float Aa = -__expf(A_log[(d0+dl)*8 + n]);
    float h = Hi[(((size_t)chunk*BATCH + b)*DIMC + d0+dl)*8 + n];
    for (int t = 0; t < 64; t++) {
        float dtv = sdt[dl][t];
        float dA  = __expf(dtv * Aa);
        h = h*dA + dtv * sx[dl][t] * sB[n][t];
        float yv = h * sC[n][t];
        yv += __shfl_down_sync(0xffffffffu, yv, 4);
        yv += __shfl_down_sync(0xffffffffu, yv, 2);
        yv += __shfl_down_sync(0xffffffffu, yv, 1);
        if (n == 0) sy[dl][t] = yv;
    }
    __syncthreads();
    for (int i = tid; i < 2048; i += 256) {
        int r = i >> 6, c = i & 63;
        int tl = chunk*64 + c;
        int lp = rev ? (LSEQ-1-tl) : tl;
        size_t gi = ((size_t)(b*DIMC + d0 + r))*LSEQ + lp;
        float v = sy[r][c] + sx[r][c]*Dp[d0+r];
        float zz = z[gi];
        y[gi] = v * zz * sigmoidf_(zz);
    }
}

// ---------------- rmsnorm for 3 heads -> token-major bf16 hi/lo (vectorized) ----------------
__global__ void rms3_k(const float* __restrict__ yf, const float* __restrict__ yb,
                       const float* __restrict__ w,
                       __nv_bfloat16* __restrict__ ynh, __nv_bfloat16* __restrict__ ynl)
{
    int idx = blockIdx.x * blockDim.x + threadIdx.x;
    int b = idx >> 12, l = idx & (LSEQ-1);
    size_t base = (size_t)b*DIMC*LSEQ + l;
    float sa = 0.f, sf = 0.f, sb = 0.f;
    #pragma unroll 8
    for (int d = 0; d < DIMC; d++) {
        float vf = yf[base + (size_t)d*LSEQ];
        float vb = yb[base + (size_t)d*LSEQ];
        float va = 0.5f*(vf+vb);
        sa += va*va; sf += vf*vf; sb += vb*vb;
    }
    float ra = rsqrtf(sa*(1.f/DIMC) + EPS_F);
    float rf = rsqrtf(sf*(1.f/DIMC) + EPS_F);
    float rb = rsqrtf(sb*(1.f/DIMC) + EPS_F);
    size_t r0 = ((size_t)(0*2 + b)*LSEQ + l) * 256;
    size_t r1 = ((size_t)(1*2 + b)*LSEQ + l) * 256;
    size_t r2 = ((size_t)(2*2 + b)*LSEQ + l) * 256;
    for (int d0 = 0; d0 < DIMC; d0 += 8) {
        __align__(16) __nv_bfloat16 h0[8], l0[8], h1[8], l1[8], h2[8], l2[8];
        #pragma unroll
        for (int j = 0; j < 8; j++) {
            int d = d0 + j;
            float vf = yf[base + (size_t)d*LSEQ];
            float vb = yb[base + (size_t)d*LSEQ];
            float va = 0.5f*(vf+vb);
            float ww = w[d];
            bf16split(va*ra*ww, h0[j], l0[j]);
            bf16split(vf*rf*ww, h1[j], l1[j]);
            bf16split(vb*rb*ww, h2[j], l2[j]);
        }
        *(uint4*)(ynh + r0 + d0) = *(uint4*)h0; *(uint4*)(ynl + r0 + d0) = *(uint4*)l0;
        *(uint4*)(ynh + r1 + d0) = *(uint4*)h1; *(uint4*)(ynl + r1 + d0) = *(uint4*)l1;
        *(uint4*)(ynh + r2 + d0) = *(uint4*)h2; *(uint4*)(ynl + r2 + d0) = *(uint4*)l2;
    }
}

// ---------------- launch ----------------
extern "C" void kernel_launch(void* const* d_in, const int* in_sizes, int n_in,
                              void* d_out, int out_size)
{
    (void)in_sizes; (void)n_in; (void)out_size;
    const float* input0      = (const float*)d_in[0];
    const float* input1      = (const float*)d_in[1];
    const float* norm0_w     = (const float*)d_in[2];
    const float* norm0_b     = (const float*)d_in[3];
    const float* norm1_w     = (const float*)d_in[4];
    const float* norm1_b     = (const float*)d_in[5];
    const float* in_proj_w   = (const float*)d_in[6];
    const float* in_projz_w  = (const float*)d_in[7];
    const float* conv1d_w    = (const float*)d_in[8];
    const float* conv1d_bias = (const float*)d_in[9];
    const float* conv1db_w   = (const float*)d_in[10];
    const float* conv1db_bias= (const float*)d_in[11];
    const float* xproj_w     = (const float*)d_in[12];
    const float* xprojb_w    = (const float*)d_in[13];
    const float* dtproj_w    = (const float*)d_in[14];
    const float* dtproj_bias = (const float*)d_in[15];
    const float* dtprojb_w   = (const float*)d_in[16];
    const float* dtprojb_bias= (const float*)d_in[17];
    const float* A_log       = (const float*)d_in[18];
    const float* Ab_log      = (const float*)d_in[19];
    const float* D_p         = (const float*)d_in[20];
    const float* D_b         = (const float*)d_in[21];
    const float* rms_w       = (const float*)d_in[22];
    const float* out_proj_w  = (const float*)d_in[23];
    const float* conv3d_w    = (const float*)d_in[24];
    const float* conv3d_bias = (const float*)d_in[25];
    float* out = (float*)d_out;

    float *x_, *z_, *xc_, *dbl_, *dt_, *P_, *S_, *Hi_, *y_, *skipT;
    __nv_bfloat16 *s0h,*s0l,*s1h,*s1l,*ynh,*ynl,*oh,*ol;
    __nv_bfloat16 *wip_h,*wip_l,*wiz_h,*wiz_l,*wop_h,*wop_l,*wc3_h,*wc3_l;
    cudaGetSymbolAddress((void**)&x_,   g_x);
    cudaGetSymbolAddress((void**)&z_,   g_z);
    cudaGetSymbolAddress((void**)&xc_,  g_xc);
    cudaGetSymbolAddress((void**)&dbl_, g_dbl);
    cudaGetSymbolAddress((void**)&dt_,  g_dt);
    cudaGetSymbolAddress((void**)&P_,   g_P);
    cudaGetSymbolAddress((void**)&S_,   g_S);
    cudaGetSymbolAddress((void**)&Hi_,  g_Hi);
    cudaGetSymbolAddress((void**)&y_,   g_y);
    cudaGetSymbolAddress((void**)&skipT,g_skipT);
    cudaGetSymbolAddress((void**)&s0h,  g_s0h);
    cudaGetSymbolAddress((void**)&s0l,  g_s0l);
    cudaGetSymbolAddress((void**)&s1h,  g_s1h);
    cudaGetSymbolAddress((void**)&s1l,  g_s1l);
    cudaGetSymbolAddress((void**)&ynh,  g_ynh);
    cudaGetSymbolAddress((void**)&ynl,  g_ynl);
    cudaGetSymbolAddress((void**)&oh,   g_oh);
    cudaGetSymbolAddress((void**)&ol,   g_ol);
    cudaGetSymbolAddress((void**)&wip_h, g_wip_h); cudaGetSymbolAddress((void**)&wip_l, g_wip_l);
    cudaGetSymbolAddress((void**)&wiz_h, g_wiz_h); cudaGetSymbolAddress((void**)&wiz_l, g_wiz_l);
    cudaGetSymbolAddress((void**)&wop_h, g_wop_h); cudaGetSymbolAddress((void**)&wop_l, g_wop_l);
    cudaGetSymbolAddress((void**)&wc3_h, g_wc3_h); cudaGetSymbolAddress((void**)&wc3_l, g_wc3_l);

    const int TCSMEM = 4 * TILE_B;   // 73728
    cudaFuncSetAttribute(tcgemm_k<EPT_XPOSE>, cudaFuncAttributeMaxDynamicSharedMemorySize, TCSMEM);
    cudaFuncSetAttribute(tcgemm_k<EPT_SKIP>,  cudaFuncAttributeMaxDynamicSharedMemorySize, TCSMEM);
    cudaFuncSetAttribute(tcgemm_k<EPT_BIAS>,  cudaFuncAttributeMaxDynamicSharedMemorySize, TCSMEM);

    const long long SB  = (long long)DIMC*LSEQ;
    const long long SB32= (long long)32*LSEQ;
    const int SCN = 64*BATCH*DIMC*8;

    // 0) weight splits + skip transpose
    wsplit_k<<<256, 256>>>(in_proj_w,  wip_h, wip_l, 65536);
    wsplit_k<<<256, 256>>>(in_projz_w, wiz_h, wiz_l, 65536);
    wsplit_k<<<256, 256>>>(out_proj_w, wop_h, wop_l, 65536);
    wsplit_k<<<1200, 256>>>(conv3d_w,  wc3_h, wc3_l, 307200);
    xposeF_k<<<dim3(128,8,2), 256>>>(input0, skipT);

    // 1) layernorms -> token-major bf16 hi/lo
    ln_k<<<dim3(32,2), 256>>>(input0, input1, norm0_w, norm0_b, norm1_w, norm1_b,
                              s0h, s0l, s1h, s1l);

    // 2) in_proj / in_projz on tensor cores -> channel-major fp32
    tcgemm_k<EPT_XPOSE><<<dim3(2,32,2), 256, TCSMEM>>>(s0h, s0l, wip_h, wip_l, 256,
                                                       x_, nullptr, nullptr, nullptr, nullptr);
    tcgemm_k<EPT_XPOSE><<<dim3(2,32,2), 256, TCSMEM>>>(s1h, s1l, wiz_h, wiz_l, 256,
                                                       z_, nullptr, nullptr, nullptr, nullptr);

    for (int dir = 0; dir < 2; dir++) {
        float* xcD  = xc_  + (size_t)dir*BATCH*DIMC*LSEQ;
        float* dblD = dbl_ + (size_t)dir*BATCH*32*LSEQ;
        float* dtD  = dt_  + (size_t)dir*BATCH*DIMC*LSEQ;
        float* PD   = P_   + (size_t)dir*SCN;
        float* SD   = S_   + (size_t)dir*SCN;
        float* HiD  = Hi_  + (size_t)dir*SCN;
        float* yD   = y_   + (size_t)dir*BATCH*DIMC*LSEQ;
        const float* cw = dir ? conv1db_w    : conv1d_w;
        const float* cb = dir ? conv1db_bias : conv1d_bias;
        const float* xw = dir ? xprojb_w     : xproj_w;
        const float* dw = dir ? dtprojb_w    : dtproj_w;
        const float* db = dir ? dtprojb_bias : dtproj_bias;
        const float* al = dir ? Ab_log       : A_log;
        const float* Dd = dir ? D_b          : D_p;

        conv_silu_k<<<dim3(16,512), 256>>>(x_, cw, cb, xcD, dir);
        sgemm_k<EP_NONE><<<dim3(32,1,2), 256>>>(xw, 256, 0, xcD, LSEQ, SB,
                                                dblD, LSEQ, SB32, 32, 256, nullptr);
        sgemm_k<EP_SPBIAS><<<dim3(32,2,2), 256>>>(dw, 16, 0, dblD, LSEQ, SB32,
                                                  dtD, LSEQ, SB, 256, 16, db);
        scanA_k<<<dim3(64,2,8), 256>>>(dtD, xcD, dblD, al, PD, SD);
        scanB_k<<<16, 256>>>(PD, SD, HiD);
        scanC_k<<<dim3(64,2,8), 256>>>(dtD, xcD, dblD, al, HiD, Dd, z_, yD, dir);
    }

    // 7) rmsnorm 3 heads -> token-major bf16 hi/lo
    rms3_k<<<32, 256>>>(y_, y_ + (size_t)BATCH*DIMC*LSEQ, rms_w, ynh, ynl);

    // 8) out_proj (+skip) on tensor cores -> o hi/lo (token-major bf16)
    tcgemm_k<EPT_SKIP><<<dim3(2,32,6), 256, TCSMEM>>>(ynh, ynl, wop_h, wop_l, 256,
                                                      nullptr, nullptr, skipT, oh, ol);

    // 9) conv3d on tensor cores (+bias) -> final output (channel-major fp32)
    tcgemm_k<EPT_BIAS><<<dim3(10,32,6), 256, TCSMEM>>>(oh, ol, wc3_h, wc3_l, 1200,
                                                       out, conv3d_bias, nullptr, nullptr, nullptr);
}

// round 10
// speedup vs baseline: 2.0771x; 1.7666x over previous
#include <cuda_runtime.h>
#include <cuda_bf16.h>
#include <cstdint>
#include <math.h>

#define LSEQ 4096
#define BATCH 2
#define DIMC 256
#define EPS_F 1e-5f
#define SCN_ (64*BATCH*DIMC*8)

// ---------------- scratch (device globals) ----------------
__device__ float g_x   [BATCH*DIMC*LSEQ];
__device__ float g_z   [BATCH*DIMC*LSEQ];
__device__ float g_xc  [2][BATCH*DIMC*LSEQ];
__device__ float g_dbl [2][BATCH*32*LSEQ];
__device__ float g_dt  [2][BATCH*DIMC*LSEQ];
__device__ float g_P   [2][SCN_];
__device__ float g_S   [2][SCN_];
__device__ float g_Hi  [2][SCN_];
__device__ float g_y   [2][BATCH*DIMC*LSEQ];
__device__ float g_skipT[BATCH*LSEQ*DIMC];

__device__ __nv_bfloat16 g_s0h[BATCH*LSEQ*DIMC], g_s0l[BATCH*LSEQ*DIMC];
__device__ __nv_bfloat16 g_s1h[BATCH*LSEQ*DIMC], g_s1l[BATCH*LSEQ*DIMC];
__device__ __nv_bfloat16 g_ynh[6*LSEQ*DIMC],     g_ynl[6*LSEQ*DIMC];
__device__ __nv_bfloat16 g_oh [6*LSEQ*DIMC],     g_ol [6*LSEQ*DIMC];
__device__ __nv_bfloat16 g_wip_h[DIMC*DIMC], g_wip_l[DIMC*DIMC];
__device__ __nv_bfloat16 g_wiz_h[DIMC*DIMC], g_wiz_l[DIMC*DIMC];
__device__ __nv_bfloat16 g_wop_h[DIMC*DIMC], g_wop_l[DIMC*DIMC];
__device__ __nv_bfloat16 g_wc3_h[1200*DIMC], g_wc3_l[1200*DIMC];

__device__ __forceinline__ float sigmoidf_(float x){ return 1.f/(1.f+__expf(-x)); }
__device__ __forceinline__ float softplusf_(float x){ return x>20.f ? x : log1pf(__expf(x)); }

__device__ __forceinline__ void bf16split(float v, __nv_bfloat16& h, __nv_bfloat16& l) {
    h = __float2bfloat16(v);
    l = __float2bfloat16(v - __bfloat162float(h));
}

__device__ __forceinline__ uint32_t smem_u32(const void* p) {
    uint32_t a;
    asm("{ .reg .u64 t; cvta.to.shared.u64 t, %1; cvt.u32.u64 %0, t; }" : "=r"(a) : "l"(p));
    return a;
}
__device__ __forceinline__ void ldmx4(uint32_t* r, uint32_t addr) {
    asm volatile("ldmatrix.sync.aligned.m8n8.x4.shared.b16 {%0,%1,%2,%3}, [%4];"
        : "=r"(r[0]),"=r"(r[1]),"=r"(r[2]),"=r"(r[3]) : "r"(addr));
}
__device__ __forceinline__ void mma16816(float* d, const uint32_t* a, uint32_t b0, uint32_t b1) {
    asm volatile("mma.sync.aligned.m16n8k16.row.col.f32.bf16.bf16.f32 "
        "{%0,%1,%2,%3}, {%4,%5,%6,%7}, {%8,%9}, {%0,%1,%2,%3};"
        : "+f"(d[0]),"+f"(d[1]),"+f"(d[2]),"+f"(d[3])
        : "r"(a[0]),"r"(a[1]),"r"(a[2]),"r"(a[3]), "r"(b0),"r"(b1));
}
__device__ __forceinline__ void cp16(uint32_t dst, const void* src, int sz) {
    asm volatile("cp.async.cg.shared.global [%0], [%1], 16, %2;"
        :: "r"(dst), "l"(__cvta_generic_to_global(src)), "r"(sz) : "memory");
}

// ---------------- split-bf16 GEMM, cp.async double-buffered ----------------
#define EPT_XPOSE 0
#define EPT_SKIP  1
#define EPT_BIAS  2
#define TILE_B 18432
#define STG    (4*TILE_B)     // one stage: Ah|Al|Bh|Bl

template<int EPT>
__global__ void __launch_bounds__(256) tcgemm_k(
    const __nv_bfloat16* __restrict__ Ah, const __nv_bfloat16* __restrict__ Al,
    const __nv_bfloat16* __restrict__ Bh, const __nv_bfloat16* __restrict__ Bl,
    int bRows,
    float* __restrict__ outF, const float* __restrict__ bias,
    const float* __restrict__ skipT,
    __nv_bfloat16* __restrict__ Oh, __nv_bfloat16* __restrict__ Ol)
{
    extern __shared__ char smem[];
    const int tid = threadIdx.x, lane = tid & 31, warp = tid >> 5;
    const int mw = warp & 3, nw = warp >> 2;
    const int n0 = blockIdx.x * 128, tl0 = blockIdx.y * 128, zb = blockIdx.z;
    const long long t0 = (long long)zb * LSEQ + tl0;

    float acc[2][8][4];
    #pragma unroll
    for (int i = 0; i < 2; i++)
        #pragma unroll
        for (int j = 0; j < 8; j++)
            #pragma unroll
            for (int c = 0; c < 4; c++) acc[i][j][c] = 0.f;

    const uint32_t sbase = smem_u32(smem);
    const int a_row  = (lane & 7) + ((lane >> 3) & 1) * 8;
    const int a_kadd = (lane >> 4) * 8;
    const int b_row  = (lane & 7) + (lane >> 4) * 8;
    const int b_kadd = ((lane >> 3) & 1) * 8;
    const uint32_t aoffH = sbase + 0        + (uint32_t)((mw*32 + a_row)*72 + a_kadd) * 2;
    const uint32_t boffH = sbase + 2*TILE_B + (uint32_t)((nw*64 + b_row)*72 + b_kadd) * 2;

    const int lrow = tid >> 3, lc8 = (tid & 7) * 8;

    auto load_chunk = [&](int kc, int stage) {
        const int kofs = kc * 64;
        const uint32_t sb0 = sbase + stage * STG;
        #pragma unroll
        for (int it = 0; it < 4; it++) {
            int row = lrow + it * 32;
            uint32_t sa = sb0 + (uint32_t)(row * 72 + lc8) * 2;
            cp16(sa,            Ah + (t0 + row) * 256 + kofs + lc8, 16);
            cp16(sa + TILE_B,   Al + (t0 + row) * 256 + kofs + lc8, 16);
            int brow = n0 + row;
            int ok = (brow < bRows) ? 16 : 0;
            if (brow >= bRows) brow = bRows - 1;
            cp16(sa + 2*TILE_B, Bh + (size_t)brow * 256 + kofs + lc8, ok);
            cp16(sa + 3*TILE_B, Bl + (size_t)brow * 256 + kofs + lc8, ok);
        }
    };

    auto compute = [&](int stage) {
        const uint32_t sadd = (uint32_t)stage * STG;
        #pragma unroll
        for (int ks = 0; ks < 4; ks++) {
            const uint32_t k2 = (uint32_t)(ks * 16) * 2;
            uint32_t aH[2][4], aL[2][4];
            #pragma unroll
            for (int i = 0; i < 2; i++) {
                ldmx4(aH[i], aoffH + sadd + i*16*144 + k2);
                ldmx4(aL[i], aoffH + sadd + TILE_B + i*16*144 + k2);
            }
            #pragma unroll
            for (int half = 0; half < 2; half++) {
                uint32_t bH[2][4], bL[2][4];
                #pragma unroll
                for (int gg = 0; gg < 2; gg++) {
                    int g = half*2 + gg;
                    ldmx4(bH[gg], boffH + sadd + g*16*144 + k2);
                    ldmx4(bL[gg], boffH + sadd + TILE_B + g*16*144 + k2);
                }
                #pragma unroll
                for (int i = 0; i < 2; i++)
                    #pragma unroll
                    for (int gg = 0; gg < 2; gg++)
                        #pragma unroll
                        for (int p = 0; p < 2; p++) {
                            int j8 = (half*2 + gg)*2 + p;
                            mma16816(acc[i][j8], aH[i], bH[gg][2*p], bH[gg][2*p+1]);
                            mma16816(acc[i][j8], aH[i], bL[gg][2*p], bL[gg][2*p+1]);
                            mma16816(acc[i][j8], aL[i], bH[gg][2*p], bH[gg][2*p+1]);
                        }
            }
        }
    };

    load_chunk(0, 0);
    asm volatile("cp.async.commit_group;" ::: "memory");
    for (int kc = 0; kc < 4; kc++) {
        if (kc < 3) {
            load_chunk(kc + 1, (kc + 1) & 1);
            asm volatile("cp.async.commit_group;" ::: "memory");
            asm volatile("cp.async.wait_group 1;" ::: "memory");
        } else {
            asm volatile("cp.async.wait_group 0;" ::: "memory");
        }
        __syncthreads();
        compute(kc & 1);
        __syncthreads();
    }

    if (EPT == EPT_SKIP) {
        #pragma unroll
        for (int i = 0; i < 2; i++)
            #pragma unroll
            for (int rr = 0; rr < 2; rr++) {
                int tok = tl0 + mw*32 + i*16 + (lane >> 2) + rr*8;
                size_t orow = ((size_t)zb * LSEQ + tok) * 256;
                size_t srow = ((size_t)(zb & 1) * LSEQ + tok) * 256;
                #pragma unroll
                for (int j8 = 0; j8 < 8; j8++) {
                    int n = n0 + nw*64 + j8*8 + 2*(lane & 3);
                    float2 sk = *(const float2*)(skipT + srow + n);
                    float v0 = acc[i][j8][rr*2+0] + sk.x;
                    float v1 = acc[i][j8][rr*2+1] + sk.y;
                    __nv_bfloat16 h0,l0,h1,l1;
                    bf16split(v0,h0,l0); bf16split(v1,h1,l1);
                    __nv_bfloat162 ph; ph.x = h0; ph.y = h1;
                    __nv_bfloat162 pl; pl.x = l0; pl.y = l1;
                    *(__nv_bfloat162*)(Oh + orow + n) = ph;
                    *(__nv_bfloat162*)(Ol + orow + n) = pl;
                }
            }
    } else {
        float* sbuf = (float*)smem;
        #pragma unroll 1
        for (int h = 0; h < 2; h++) {
            __syncthreads();
            if (nw == h) {
                #pragma unroll
                for (int i = 0; i < 2; i++)
                    #pragma unroll
                    for (int j8 = 0; j8 < 8; j8++)
                        #pragma unroll
                        for (int rr = 0; rr < 2; rr++) {
                            int tok = mw*32 + i*16 + (lane >> 2) + rr*8;
                            int nl = j8*8 + 2*(lane & 3);
                            sbuf[nl*132 + tok]     = acc[i][j8][rr*2+0];
                            sbuf[(nl+1)*132 + tok] = acc[i][j8][rr*2+1];
                        }
            }
            __syncthreads();
            int row = tid >> 2;
            int n = n0 + h*64 + row;
            if (n < bRows) {
                float bv = (EPT == EPT_BIAS) ? bias[n] : 0.f;
                const float* srcr = sbuf + row*132;
                float* dstr = outF + ((size_t)zb * bRows + n) * LSEQ + tl0;
                int c0 = (tid & 3) * 4;
                #pragma unroll
                for (int q = 0; q < 8; q++) {
                    int col = c0 + q*16;
                    float4 v = *(const float4*)(srcr + col);
                    v.x += bv; v.y += bv; v.z += bv; v.w += bv;
                    *(float4*)(dstr + col) = v;
                }
            }
        }
    }
}

// ---------------- fused weight bf16 split (4 segments) ----------------
__global__ void wsplit4_k(const float* __restrict__ w0, const float* __restrict__ w1,
                          const float* __restrict__ w2, const float* __restrict__ w3,
                          __nv_bfloat16* __restrict__ h0, __nv_bfloat16* __restrict__ l0,
                          __nv_bfloat16* __restrict__ h1, __nv_bfloat16* __restrict__ l1,
                          __nv_bfloat16* __restrict__ h2, __nv_bfloat16* __restrict__ l2,
                          __nv_bfloat16* __restrict__ h3, __nv_bfloat16* __restrict__ l3)
{
    int seg = blockIdx.y;
    const float* w = seg==0?w0 : seg==1?w1 : seg==2?w2 : w3;
    __nv_bfloat16* h = seg==0?h0 : seg==1?h1 : seg==2?h2 : h3;
    __nv_bfloat16* l = seg==0?l0 : seg==1?l1 : seg==2?l2 : l3;
    int n = (seg < 3) ? 65536 : 307200;
    int i = blockIdx.x * blockDim.x + threadIdx.x;
    if (i < n) { __nv_bfloat16 hh, ll; bf16split(w[i], hh, ll); h[i] = hh; l[i] = ll; }
}

// ---------------- transpose input0 -> token-major fp32 ----------------
__global__ void xposeF_k(const float* __restrict__ in, float* __restrict__ out)
{
    __shared__ float t[32][33];
    int b = blockIdx.z;
    int tok0 = blockIdx.x * 32, ch0 = blockIdx.y * 32;
    int lx = threadIdx.x & 31, ly = threadIdx.x >> 5;
    #pragma unroll
    for (int i = 0; i < 4; i++) {
        int ch = ch0 + ly + i*8;
        t[lx][ly + i*8] = in[((size_t)b*256 + ch)*LSEQ + tok0 + lx];
    }
    __syncthreads();
    #pragma unroll
    for (int i = 0; i < 4; i++) {
        int tok = tok0 + ly + i*8;
        out[((size_t)b*LSEQ + tok)*256 + ch0 + lx] = t[ly + i*8][lx];
    }
}

// ---------------- layernorm -> token-major bf16 hi/lo ----------------
__global__ void ln_k(const float* __restrict__ in0, const float* __restrict__ in1,
                     const float* __restrict__ w0, const float* __restrict__ b0,
                     const float* __restrict__ w1, const float* __restrict__ b1,
                     __nv_bfloat16* __restrict__ s0h, __nv_bfloat16* __restrict__ s0l,
                     __nv_bfloat16* __restrict__ s1h, __nv_bfloat16* __restrict__ s1l)
{
    int which = blockIdx.y;
    const float* in = which ? in1 : in0;
    const float* w  = which ? w1  : w0;
    const float* bb = which ? b1  : b0;
    __nv_bfloat16* oh = which ? s1h : s0h;
    __nv_bfloat16* ol = which ? s1l : s0l;
    int idx = blockIdx.x * blockDim.x + threadIdx.x;
    int b = idx >> 12, l = idx & (LSEQ-1);
    const float* p = in + (size_t)b*DIMC*LSEQ + l;
    float s = 0.f, s2 = 0.f;
    #pragma unroll 8
    for (int c = 0; c < DIMC; c++) { float v = p[(size_t)c*LSEQ]; s += v; s2 += v*v; }
    float mean = s * (1.f/DIMC);
    float var  = s2 * (1.f/DIMC) - mean*mean;
    float rstd = rsqrtf(var + EPS_F);
    size_t ob = (size_t)idx * 256;
    for (int c0 = 0; c0 < DIMC; c0 += 8) {
        __align__(16) __nv_bfloat16 hh[8], ll[8];
        #pragma unroll
        for (int j = 0; j < 8; j++) {
            float v = (p[(size_t)(c0+j)*LSEQ] - mean) * rstd * w[c0+j] + bb[c0+j];
            bf16split(v, hh[j], ll[j]);
        }
        *(uint4*)(oh + ob + c0) = *(uint4*)hh;
        *(uint4*)(ol + ob + c0) = *(uint4*)ll;
    }
}

// ---------------- depthwise causal conv (K=4) + silu — both dirs ----------------
__global__ void conv_silu_k(const float* __restrict__ x,
                            const float* __restrict__ wf, const float* __restrict__ bf,
                            const float* __restrict__ wb, const float* __restrict__ bbias,
                            float* __restrict__ xc)
{
    int t   = blockIdx.x * blockDim.x + threadIdx.x;
    int bdd = blockIdx.y;                 // dir*512 + b*256 + d
    int dir = bdd >> 9;
    int bd  = bdd & 511;
    int d   = bd & 255;
    const float* w  = dir ? wb : wf;
    const float* bi = dir ? bbias : bf;
    const float* xp = x + (size_t)bd*LSEQ;
    float acc = bi[d];
    #pragma unroll
    for (int k = 0; k < 4; k++) {
        int s = t - 3 + k;
        if (s >= 0) {
            int ph = dir ? (LSEQ-1-s) : s;
            acc += w[d*4+k] * xp[ph];
        }
    }
    xc[(size_t)bdd*LSEQ + t] = acc * sigmoidf_(acc);
}

// ---------------- fp32 SGEMM (xproj / dtproj), per-dir weight select ----------------
enum { EP_NONE=0, EP_SPBIAS=1 };

template<int EP>
__global__ void __launch_bounds__(256) sgemm_k(
    const float* __restrict__ A0, const float* __restrict__ A1, int lda,
    const float* __restrict__ B, int ldb, long long bStride,
    float* __restrict__ C, int ldc, long long cStride,
    int M, int Kdim,
    const float* __restrict__ bias0, const float* __restrict__ bias1)
{
    __shared__ float As[8][128];
    __shared__ float Bs[8][128];
    int zb = blockIdx.z;
    int dir = zb >> 1;
    const float* A = dir ? A1 : A0;
    const float* bias = dir ? bias1 : bias0;
    B += (size_t)zb * bStride;
    C += (size_t)zb * cStride;

    int m0 = blockIdx.y * 128;
    int n0 = blockIdx.x * 128;
    int tid = threadIdx.x;
    int ar  = tid >> 1, ac = (tid & 1) << 2;
    int brr = tid >> 5, bc = (tid & 31) << 2;
    int mt0 = (tid >> 4) << 2, nt0 = (tid & 15) << 2;

    unsigned long long acc[8][4];
    #pragma unroll
    for (int i = 0; i < 8; i++)
        #pragma unroll
        for (int j = 0; j < 4; j++) acc[i][j] = 0ull;

    for (int k0 = 0; k0 < Kdim; k0 += 8) {
        float4 a4 = make_float4(0.f,0.f,0.f,0.f);
        int arow = m0 + ar;
        if (arow < M) a4 = *(const float4*)(A + (size_t)arow*lda + (k0 + ac));
        As[ac+0][ar] = a4.x; As[ac+1][ar] = a4.y; As[ac+2][ar] = a4.z; As[ac+3][ar] = a4.w;
        float4 b4 = *(const float4*)(B + (size_t)(k0 + brr)*ldb + (n0 + bc));
        *(float4*)&Bs[brr][bc] = b4;
        __syncthreads();
        #pragma unroll
        for (int kk = 0; kk < 8; kk++) {
            float4 aL = *(const float4*)&As[kk][mt0];
            float4 aH = *(const float4*)&As[kk][mt0+64];
            float av[8] = {aL.x,aL.y,aL.z,aL.w,aH.x,aH.y,aH.z,aH.w};
            unsigned long long b2[4];
            const unsigned long long* bpL = (const unsigned long long*)&Bs[kk][nt0];
            const unsigned long long* bpH = (const unsigned long long*)&Bs[kk][nt0+64];
            b2[0] = bpL[0]; b2[1] = bpL[1]; b2[2] = bpH[0]; b2[3] = bpH[1];
            #pragma unroll
            for (int i = 0; i < 8; i++) {
                unsigned long long a2;
                asm("mov.b64 %0, {%1, %1};" : "=l"(a2) : "f"(av[i]));
                #pragma unroll
                for (int j = 0; j < 4; j++)
                    asm("fma.rn.f32x2 %0, %1, %2, %0;" : "+l"(acc[i][j]) : "l"(a2), "l"(b2[j]));
            }
        }
        __syncthreads();
    }

    #pragma unroll
    for (int i = 0; i < 8; i++) {
        int m = m0 + ((i < 4) ? (mt0 + i) : (64 + mt0 + i - 4));
        if (m >= M) continue;
        float bv = (EP == EP_SPBIAS) ? bias[m] : 0.f;
        #pragma unroll
        for (int j = 0; j < 4; j++) {
            int n = n0 + ((j < 2) ? (nt0 + 2*j) : (64 + nt0 + 2*(j-2)));
            float2 v;
            asm("mov.b64 {%0, %1}, %2;" : "=f"(v.x), "=f"(v.y) : "l"(acc[i][j]));
            if (EP == EP_SPBIAS) { v.x = softplusf_(v.x + bv); v.y = softplusf_(v.y + bv); }
            *(float2*)(C + (size_t)m*ldc + n) = v;
        }
    }
}

// ---------------- chunked selective scan (both dirs in one launch) ----------------
__global__ void __launch_bounds__(256) scanA_k(
    const float* __restrict__ dt, const float* __restrict__ xc,
    const float* __restrict__ dbl,
    const float* __restrict__ A0, const float* __restrict__ A1,
    float* __restrict__ P, float* __restrict__ S)
{
    __shared__ float sdt[32][65], sx[32][65], sB[8][65];
    int chunk = blockIdx.x, zd = blockIdx.y, d0 = blockIdx.z * 32;
    int dir = zd >> 1, b = zd & 1;
    const float* Alog = dir ? A1 : A0;
    int tid = threadIdx.x;
    size_t base = ((size_t)(zd*DIMC + d0))*LSEQ + chunk*64;
    for (int i = tid; i < 2048; i += 256) {
        int r = i >> 6, c = i & 63;
        sdt[r][c] = dt[base + (size_t)r*LSEQ + c];
        sx [r][c] = xc[base + (size_t)r*LSEQ + c];
    }
    size_t bbase = ((size_t)(zd*32 + 16))*LSEQ + chunk*64;
    for (int i = tid; i < 512; i += 256) {
        int r = i >> 6, c = i & 63;
        sB[r][c] = dbl[bbase + (size_t)r*LSEQ + c];
    }
    __syncthreads();
    int dl = tid >> 3, n = tid & 7;
    float Aa = -__expf(Alog[(d0+dl)*8 + n]);
    float Pv = 1.f, Sv = 0.f;
    #pragma unroll 8
    for (int t = 0; t < 64; t++) {
        float dtv = sdt[dl][t];
        float dA  = __expf(dtv * Aa);
        Sv = Sv*dA + dtv * sx[dl][t] * sB[n][t];
        Pv *= dA;
    }
    size_t o = (size_t)dir*SCN_ + (((size_t)chunk*BATCH + b)*DIMC + d0+dl)*8 + n;
    P[o] = Pv; S[o] = Sv;
}

__global__ void scanB_k(const float* __restrict__ P, const float* __restrict__ S,
                        float* __restrict__ Hi)
{
    int gid = blockIdx.x * blockDim.x + threadIdx.x;   // 0..8191
    int dir = gid >> 12, idx = gid & 4095;
    const float* Pd = P + (size_t)dir*SCN_;
    const float* Sd = S + (size_t)dir*SCN_;
    float* Hd = Hi + (size_t)dir*SCN_;
    float h = 0.f;
    for (int c0 = 0; c0 < 64; c0 += 8) {
        float p[8], s[8];
        #pragma unroll
        for (int j = 0; j < 8; j++) {
            size_t o = (size_t)(c0+j)*4096 + idx;
            p[j] = Pd[o]; s[j] = Sd[o];
        }
        #pragma unroll
        for (int j = 0; j < 8; j++) {
            Hd[(size_t)(c0+j)*4096 + idx] = h;
            h = h * p[j] + s[j];
        }
    }
}

__global__ void __launch_bounds__(256) scanC_k(
    const float* __restrict__ dt, const float* __restrict__ xc,
    const float* __restrict__ dbl,
    const float* __restrict__ A0, const float* __restrict__ A1,
    const float* __restrict__ Hi,
    const float* __restrict__ D0, const float* __restrict__ D1,
    const float* __restrict__ z, float* __restrict__ y)
{
    __shared__ float sdt[32][65], sx[32][65], sB[8][65], sC[8][65];
    __shared__ float sy[32][64];
    int chunk = blockIdx.x, zd = blockIdx.y, d0 = blockIdx.z * 32;
    int dir = zd >> 1, b = zd & 1;
    const float* Alog = dir ? A1 : A0;
    const float* Dp   = dir ? D1 : D0;
    int tid = threadIdx.x;
    size_t base = ((size_t)(zd*DIMC + d0))*LSEQ + chunk*64;
    for (int i = tid; i < 2048; i += 256) {
        int r = i >> 6, c = i & 63;
        sdt[r][c] = dt[base + (size_t)r*LSEQ + c];
        sx [r][c] = xc[base + (size_t)r*LSEQ + c];
    }
    size_t bbase = ((size_t)(zd*32 + 16))*LSEQ + chunk*64;
    size_t cbase = ((size_t)(zd*32 + 24))*LSEQ + chunk*64;
    for (int i = tid; i < 512; i += 256) {
        int r = i >> 6, c = i & 63;
        sB[r][c] = dbl[bbase + (size_t)r*LSEQ + c];
        sC[r][c] = dbl[cbase + (size_t)r*LSEQ + c];
    }
    __syncthreads();
    int dl = tid >> 3, n = tid & 7;
    float Aa = -__expf(Alog[(d0+dl)*8 + n]);
    float h = Hi[(size_t)dir*SCN_ + (((size_t)chunk*BATCH + b)*DIMC + d0+dl)*8 + n];
    for (int t = 0; t < 64; t++) {
        float dtv = sdt[dl][t];
        float dA  = __expf(dtv * Aa);
        h = h*dA + dtv * sx[dl][t] * sB[n][t];
        float yv = h * sC[n][t];
        yv += __shfl_down_sync(0xffffffffu, yv, 4);
        yv += __shfl_down_sync(0xffffffffu, yv, 2);
        yv += __shfl_down_sync(0xffffffffu, yv, 1);
        if (n == 0) sy[dl][t] = yv;
    }
    __syncthreads();
    float* yD = y + (size_t)dir * BATCH*DIMC*LSEQ;
    for (int i = tid; i < 2048; i += 256) {
        int r = i >> 6, c = i & 63;
        int tl = chunk*64 + c;
        int lp = dir ? (LSEQ-1-tl) : tl;
        size_t gi = ((size_t)(b*DIMC + d0 + r))*LSEQ + lp;
        float v = sy[r][c] + sx[r][c]*Dp[d0+r];
        float zz = z[gi];
        yD[gi] = v * zz * sigmoidf_(zz);
    }
}

// ---------------- rmsnorm 3 heads -> token-major bf16 hi/lo ----------------
__global__ void rms3_k(const float* __restrict__ yf, const float* __restrict__ yb,
                       const float* __restrict__ w,
                       __nv_bfloat16* __restrict__ ynh, __nv_bfloat16* __restrict__ ynl)
{
    int idx = blockIdx.x * blockDim.x + threadIdx.x;
    int b = idx >> 12, l = idx & (LSEQ-1);
    size_t base = (size_t)b*DIMC*LSEQ + l;
    float sa = 0.f, sf = 0.f, sb = 0.f;
    #pragma unroll 8
    for (int d = 0; d < DIMC; d++) {
        float vf = yf[base + (size_t)d*LSEQ];
        float vb = yb[base + (size_t)d*LSEQ];
        float va = 0.5f*(vf+vb);
        sa += va*va; sf += vf*vf; sb += vb*vb;
    }
    float ra = rsqrtf(sa*(1.f/DIMC) + EPS_F);
    float rf = rsqrtf(sf*(1.f/DIMC) + EPS_F);
    float rb = rsqrtf(sb*(1.f/DIMC) + EPS_F);
    size_t r0 = ((size_t)(0*2 + b)*LSEQ + l) * 256;
    size_t r1 = ((size_t)(1*2 + b)*LSEQ + l) * 256;
    size_t r2 = ((size_t)(2*2 + b)*LSEQ + l) * 256;
    for (int d0 = 0; d0 < DIMC; d0 += 8) {
        __align__(16) __nv_bfloat16 h0[8], l0[8], h1[8], l1[8], h2[8], l2[8];
        #pragma unroll
        for (int j = 0; j < 8; j++) {
            int d = d0 + j;
            float vf = yf[base + (size_t)d*LSEQ];
            float vb = yb[base + (size_t)d*LSEQ];
            float va = 0.5f*(vf+vb);
            float ww = w[d];
            bf16split(va*ra*ww, h0[j], l0[j]);
            bf16split(vf*rf*ww, h1[j], l1[j]);
            bf16split(vb*rb*ww, h2[j], l2[j]);
        }
        *(uint4*)(ynh + r0 + d0) = *(uint4*)h0; *(uint4*)(ynl + r0 + d0) = *(uint4*)l0;
        *(uint4*)(ynh + r1 + d0) = *(uint4*)h1; *(uint4*)(ynl + r1 + d0) = *(uint4*)l1;
        *(uint4*)(ynh + r2 + d0) = *(uint4*)h2; *(uint4*)(ynl + r2 + d0) = *(uint4*)l2;
    }
}

// ---------------- launch ----------------
extern "C" void kernel_launch(void* const* d_in, const int* in_sizes, int n_in,
                              void* d_out, int out_size)
{
    (void)in_sizes; (void)n_in; (void)out_size;
    const float* input0      = (const float*)d_in[0];
    const float* input1      = (const float*)d_in[1];
    const float* norm0_w     = (const float*)d_in[2];
    const float* norm0_b     = (const float*)d_in[3];
    const float* norm1_w     = (const float*)d_in[4];
    const float* norm1_b     = (const float*)d_in[5];
    const float* in_proj_w   = (const float*)d_in[6];
    const float* in_projz_w  = (const float*)d_in[7];
    const float* conv1d_w    = (const float*)d_in[8];
    const float* conv1d_bias = (const float*)d_in[9];
    const float* conv1db_w   = (const float*)d_in[10];
    const float* conv1db_bias= (const float*)d_in[11];
    const float* xproj_w     = (const float*)d_in[12];
    const float* xprojb_w    = (const float*)d_in[13];
    const float* dtproj_w    = (const float*)d_in[14];
    const float* dtproj_bias = (const float*)d_in[15];
    const float* dtprojb_w   = (const float*)d_in[16];
    const float* dtprojb_bias= (const float*)d_in[17];
    const float* A_log       = (const float*)d_in[18];
    const float* Ab_log      = (const float*)d_in[19];
    const float* D_p         = (const float*)d_in[20];
    const float* D_b         = (const float*)d_in[21];
    const float* rms_w       = (const float*)d_in[22];
    const float* out_proj_w  = (const float*)d_in[23];
    const float* conv3d_w    = (const float*)d_in[24];
    const float* conv3d_bias = (const float*)d_in[25];
    float* out = (float*)d_out;

    float *x_, *z_, *xc_, *dbl_, *dt_, *P_, *S_, *Hi_, *y_, *skipT;
    __nv_bfloat16 *s0h,*s0l,*s1h,*s1l,*ynh,*ynl,*oh,*ol;
    __nv_bfloat16 *wip_h,*wip_l,*wiz_h,*wiz_l,*wop_h,*wop_l,*wc3_h,*wc3_l;
    cudaGetSymbolAddress((void**)&x_,   g_x);
    cudaGetSymbolAddress((void**)&z_,   g_z);
    cudaGetSymbolAddress((void**)&xc_,  g_xc);
    cudaGetSymbolAddress((void**)&dbl_, g_dbl);
    cudaGetSymbolAddress((void**)&dt_,  g_dt);
    cudaGetSymbolAddress((void**)&P_,   g_P);
    cudaGetSymbolAddress((void**)&S_,   g_S);
    cudaGetSymbolAddress((void**)&Hi_,  g_Hi);
    cudaGetSymbolAddress((void**)&y_,   g_y);
    cudaGetSymbolAddress((void**)&skipT,g_skipT);
    cudaGetSymbolAddress((void**)&s0h,  g_s0h);
    cudaGetSymbolAddress((void**)&s0l,  g_s0l);
    cudaGetSymbolAddress((void**)&s1h,  g_s1h);
    cudaGetSymbolAddress((void**)&s1l,  g_s1l);
    cudaGetSymbolAddress((void**)&ynh,  g_ynh);
    cudaGetSymbolAddress((void**)&ynl,  g_ynl);
    cudaGetSymbolAddress((void**)&oh,   g_oh);
    cudaGetSymbolAddress((void**)&ol,   g_ol);
    cudaGetSymbolAddress((void**)&wip_h, g_wip_h); cudaGetSymbolAddress((void**)&wip_l, g_wip_l);
    cudaGetSymbolAddress((void**)&wiz_h, g_wiz_h); cudaGetSymbolAddress((void**)&wiz_l, g_wiz_l);
    cudaGetSymbolAddress((void**)&wop_h, g_wop_h); cudaGetSymbolAddress((void**)&wop_l, g_wop_l);
    cudaGetSymbolAddress((void**)&wc3_h, g_wc3_h); cudaGetSymbolAddress((void**)&wc3_l, g_wc3_l);

    const int TCSMEM = 2 * STG;   // 147456 (double-buffered)
    cudaFuncSetAttribute(tcgemm_k<EPT_XPOSE>, cudaFuncAttributeMaxDynamicSharedMemorySize, TCSMEM);
    cudaFuncSetAttribute(tcgemm_k<EPT_SKIP>,  cudaFuncAttributeMaxDynamicSharedMemorySize, TCSMEM);
    cudaFuncSetAttribute(tcgemm_k<EPT_BIAS>,  cudaFuncAttributeMaxDynamicSharedMemorySize, TCSMEM);

    const long long SB  = (long long)DIMC*LSEQ;
    const long long SB32= (long long)32*LSEQ;

    // 0) fused weight splits + skip transpose
    wsplit4_k<<<dim3(1200,4), 256>>>(in_proj_w, in_projz_w, out_proj_w, conv3d_w,
                                     wip_h, wip_l, wiz_h, wiz_l, wop_h, wop_l, wc3_h, wc3_l);
    xposeF_k<<<dim3(128,8,2), 256>>>(input0, skipT);

    // 1) layernorms -> token-major bf16 hi/lo
    ln_k<<<dim3(32,2), 256>>>(input0, input1, norm0_w, norm0_b, norm1_w, norm1_b,
                              s0h, s0l, s1h, s1l);

    // 2) in_proj / in_projz on tensor cores -> channel-major fp32
    tcgemm_k<EPT_XPOSE><<<dim3(2,32,2), 256, TCSMEM>>>(s0h, s0l, wip_h, wip_l, 256,
                                                       x_, nullptr, nullptr, nullptr, nullptr);
    tcgemm_k<EPT_XPOSE><<<dim3(2,32,2), 256, TCSMEM>>>(s1h, s1l, wiz_h, wiz_l, 256,
                                                       z_, nullptr, nullptr, nullptr, nullptr);

    // 3) conv + silu, both dirs
    conv_silu_k<<<dim3(16,1024), 256>>>(x_, conv1d_w, conv1d_bias, conv1db_w, conv1db_bias,
                                        (float*)xc_);
    // 4) xproj, both dirs
    sgemm_k<EP_NONE><<<dim3(32,1,4), 256>>>(xproj_w, xprojb_w, 256,
                                            xc_, LSEQ, SB, dbl_, LSEQ, SB32,
                                            32, 256, nullptr, nullptr);
    // 5) dtproj + softplus, both dirs
    sgemm_k<EP_SPBIAS><<<dim3(32,2,4), 256>>>(dtproj_w, dtprojb_w, 16,
                                              dbl_, LSEQ, SB32, dt_, LSEQ, SB,
                                              256, 16, dtproj_bias, dtprojb_bias);
    // 6) chunked scan, both dirs
    scanA_k<<<dim3(64,4,8), 256>>>(dt_, xc_, dbl_, A_log, Ab_log, P_, S_);
    scanB_k<<<32, 256>>>(P_, S_, Hi_);
    scanC_k<<<dim3(64,4,8), 256>>>(dt_, xc_, dbl_, A_log, Ab_log, Hi_, D_p, D_b, z_, y_);

    // 7) rmsnorm 3 heads
    rms3_k<<<32, 256>>>(y_, y_ + (size_t)BATCH*DIMC*LSEQ, rms_w, ynh, ynl);

    // 8) out_proj (+skip) -> token-major bf16 hi/lo
    tcgemm_k<EPT_SKIP><<<dim3(2,32,6), 256, TCSMEM>>>(ynh, ynl, wop_h, wop_l, 256,
                                                      nullptr, nullptr, skipT, oh, ol);

    // 9) conv3d (+bias) -> final output (channel-major fp32)
    tcgemm_k<EPT_BIAS><<<dim3(10,32,6), 256, TCSMEM>>>(oh, ol, wc3_h, wc3_l, 1200,
                                                       out, conv3d_bias, nullptr, nullptr, nullptr);
}

// round 11
// speedup vs baseline: 2.1305x; 1.0257x over previous
#include <cuda_runtime.h>
#include <cuda_bf16.h>
#include <cstdint>
#include <math.h>

#define LSEQ 4096
#define BATCH 2
#define DIMC 256
#define EPS_F 1e-5f
#define SCN_ (64*BATCH*DIMC*8)

// ---------------- scratch (device globals) ----------------
__device__ float g_x   [BATCH*DIMC*LSEQ];
__device__ float g_z   [BATCH*DIMC*LSEQ];
__device__ float g_xc  [2][BATCH*DIMC*LSEQ];
__device__ float g_dbl [2][BATCH*32*LSEQ];
__device__ float g_dt  [2][BATCH*DIMC*LSEQ];
__device__ float g_P   [2][SCN_];
__device__ float g_S   [2][SCN_];
__device__ float g_Hi  [2][SCN_];
__device__ float g_y   [2][BATCH*DIMC*LSEQ];
__device__ float g_skipT[BATCH*LSEQ*DIMC];

__device__ __nv_bfloat16 g_s0h[BATCH*LSEQ*DIMC], g_s0l[BATCH*LSEQ*DIMC];
__device__ __nv_bfloat16 g_s1h[BATCH*LSEQ*DIMC], g_s1l[BATCH*LSEQ*DIMC];
__device__ __nv_bfloat16 g_ynh[6*LSEQ*DIMC],     g_ynl[6*LSEQ*DIMC];
__device__ __nv_bfloat16 g_oh [6*LSEQ*DIMC],     g_ol [6*LSEQ*DIMC];
__device__ __nv_bfloat16 g_wip_h[DIMC*DIMC], g_wip_l[DIMC*DIMC];
__device__ __nv_bfloat16 g_wiz_h[DIMC*DIMC], g_wiz_l[DIMC*DIMC];
__device__ __nv_bfloat16 g_wop_h[DIMC*DIMC], g_wop_l[DIMC*DIMC];
__device__ __nv_bfloat16 g_wc3_h[1200*DIMC], g_wc3_l[1200*DIMC];

__device__ __forceinline__ float sigmoidf_(float x){ return 1.f/(1.f+__expf(-x)); }
__device__ __forceinline__ float softplusf_(float x){ return x>20.f ? x : log1pf(__expf(x)); }

__device__ __forceinline__ void bf16split(float v, __nv_bfloat16& h, __nv_bfloat16& l) {
    h = __float2bfloat16(v);
    l = __float2bfloat16(v - __bfloat162float(h));
}

__device__ __forceinline__ uint32_t smem_u32(const void* p) {
    uint32_t a;
    asm("{ .reg .u64 t; cvta.to.shared.u64 t, %1; cvt.u32.u64 %0, t; }" : "=r"(a) : "l"(p));
    return a;
}
__device__ __forceinline__ void ldmx4(uint32_t* r, uint32_t addr) {
    asm volatile("ldmatrix.sync.aligned.m8n8.x4.shared.b16 {%0,%1,%2,%3}, [%4];"
        : "=r"(r[0]),"=r"(r[1]),"=r"(r[2]),"=r"(r[3]) : "r"(addr));
}
__device__ __forceinline__ void mma16816(float* d, const uint32_t* a, uint32_t b0, uint32_t b1) {
    asm volatile("mma.sync.aligned.m16n8k16.row.col.f32.bf16.bf16.f32 "
        "{%0,%1,%2,%3}, {%4,%5,%6,%7}, {%8,%9}, {%0,%1,%2,%3};"
        : "+f"(d[0]),"+f"(d[1]),"+f"(d[2]),"+f"(d[3])
        : "r"(a[0]),"r"(a[1]),"r"(a[2]),"r"(a[3]), "r"(b0),"r"(b1));
}
__device__ __forceinline__ void cp16(uint32_t dst, const void* src, int sz) {
    asm volatile("cp.async.cg.shared.global [%0], [%1], 16, %2;"
        :: "r"(dst), "l"(__cvta_generic_to_global(src)), "r"(sz) : "memory");
}

// ---------------- split-bf16 GEMM, cp.async double-buffered, 128x64 tile ----------------
// 8 warps: (mw 0..3)x(nw 0..1); warp tile 32(M) x 32(N). 2 CTAs/SM (110.6KB smem).
#define EPT_XPOSE 0
#define EPT_SKIP  1
#define EPT_BIAS  2
#define TILE_A  18432            // 128 rows x 72 halves x 2B
#define TILE_BB 9216             // 64 rows x 72 halves x 2B
#define STG     (2*TILE_A + 2*TILE_BB)   // Ah|Al|Bh|Bl = 55296

template<int EPT>
__global__ void __launch_bounds__(256, 2) tcgemm_k(
    const __nv_bfloat16* __restrict__ Ah, const __nv_bfloat16* __restrict__ Al,
    const __nv_bfloat16* __restrict__ Bh, const __nv_bfloat16* __restrict__ Bl,
    int bRows,
    float* __restrict__ outF, const float* __restrict__ bias,
    const float* __restrict__ skipT,
    __nv_bfloat16* __restrict__ Oh, __nv_bfloat16* __restrict__ Ol)
{
    extern __shared__ char smem[];
    const int tid = threadIdx.x, lane = tid & 31, warp = tid >> 5;
    const int mw = warp & 3, nw = warp >> 2;
    const int n0 = blockIdx.x * 64, tl0 = blockIdx.y * 128, zb = blockIdx.z;
    const long long t0 = (long long)zb * LSEQ + tl0;

    float acc[2][4][4];
    #pragma unroll
    for (int i = 0; i < 2; i++)
        #pragma unroll
        for (int j = 0; j < 4; j++)
            #pragma unroll
            for (int c = 0; c < 4; c++) acc[i][j][c] = 0.f;

    const uint32_t sbase = smem_u32(smem);
    const int a_row  = (lane & 7) + ((lane >> 3) & 1) * 8;
    const int a_kadd = (lane >> 4) * 8;
    const int b_row  = (lane & 7) + (lane >> 4) * 8;
    const int b_kadd = ((lane >> 3) & 1) * 8;
    const uint32_t aoffH = sbase + 0        + (uint32_t)((mw*32 + a_row)*72 + a_kadd) * 2;
    const uint32_t boffH = sbase + 2*TILE_A + (uint32_t)((nw*32 + b_row)*72 + b_kadd) * 2;

    const int lrow = tid >> 3, lc8 = (tid & 7) * 8;

    auto load_chunk = [&](int kc, int stage) {
        const int kofs = kc * 64;
        const uint32_t sb0 = sbase + stage * STG;
        #pragma unroll
        for (int it = 0; it < 4; it++) {
            int row = lrow + it * 32;
            uint32_t sa = sb0 + (uint32_t)(row * 72 + lc8) * 2;
            cp16(sa,          Ah + (t0 + row) * 256 + kofs + lc8, 16);
            cp16(sa + TILE_A, Al + (t0 + row) * 256 + kofs + lc8, 16);
        }
        #pragma unroll
        for (int it = 0; it < 2; it++) {
            int row = lrow + it * 32;
            uint32_t sa = sb0 + 2*TILE_A + (uint32_t)(row * 72 + lc8) * 2;
            int brow = n0 + row;
            int ok = (brow < bRows) ? 16 : 0;
            if (brow >= bRows) brow = bRows - 1;
            cp16(sa,           Bh + (size_t)brow * 256 + kofs + lc8, ok);
            cp16(sa + TILE_BB, Bl + (size_t)brow * 256 + kofs + lc8, ok);
        }
    };

    auto compute = [&](int stage) {
        const uint32_t sadd = (uint32_t)stage * STG;
        #pragma unroll
        for (int ks = 0; ks < 4; ks++) {
            const uint32_t k2 = (uint32_t)(ks * 16) * 2;
            uint32_t aH[2][4], aL[2][4];
            #pragma unroll
            for (int i = 0; i < 2; i++) {
                ldmx4(aH[i], aoffH + sadd + i*16*144 + k2);
                ldmx4(aL[i], aoffH + sadd + TILE_A + i*16*144 + k2);
            }
            uint32_t bH[2][4], bL[2][4];
            #pragma unroll
            for (int g = 0; g < 2; g++) {
                ldmx4(bH[g], boffH + sadd + g*16*144 + k2);
                ldmx4(bL[g], boffH + sadd + TILE_BB + g*16*144 + k2);
            }
            #pragma unroll
            for (int i = 0; i < 2; i++)
                #pragma unroll
                for (int g = 0; g < 2; g++)
                    #pragma unroll
                    for (int p = 0; p < 2; p++) {
                        int j4 = g*2 + p;
                        mma16816(acc[i][j4], aH[i], bH[g][2*p], bH[g][2*p+1]);
                        mma16816(acc[i][j4], aH[i], bL[g][2*p], bL[g][2*p+1]);
                        mma16816(acc[i][j4], aL[i], bH[g][2*p], bH[g][2*p+1]);
                    }
        }
    };

    load_chunk(0, 0);
    asm volatile("cp.async.commit_group;" ::: "memory");
    for (int kc = 0; kc < 4; kc++) {
        if (kc < 3) {
            load_chunk(kc + 1, (kc + 1) & 1);
            asm volatile("cp.async.commit_group;" ::: "memory");
            asm volatile("cp.async.wait_group 1;" ::: "memory");
        } else {
            asm volatile("cp.async.wait_group 0;" ::: "memory");
        }
        __syncthreads();
        compute(kc & 1);
        __syncthreads();
    }

    if (EPT == EPT_SKIP) {
        #pragma unroll
        for (int i = 0; i < 2; i++)
            #pragma unroll
            for (int rr = 0; rr < 2; rr++) {
                int tok = tl0 + mw*32 + i*16 + (lane >> 2) + rr*8;
                size_t orow = ((size_t)zb * LSEQ + tok) * 256;
                size_t srow = ((size_t)(zb & 1) * LSEQ + tok) * 256;
                #pragma unroll
                for (int j4 = 0; j4 < 4; j4++) {
                    int n = n0 + nw*32 + j4*8 + 2*(lane & 3);
                    float2 sk = *(const float2*)(skipT + srow + n);
                    float v0 = acc[i][j4][rr*2+0] + sk.x;
                    float v1 = acc[i][j4][rr*2+1] + sk.y;
                    __nv_bfloat16 h0,l0,h1,l1;
                    bf16split(v0,h0,l0); bf16split(v1,h1,l1);
                    __nv_bfloat162 ph; ph.x = h0; ph.y = h1;
                    __nv_bfloat162 pl; pl.x = l0; pl.y = l1;
                    *(__nv_bfloat162*)(Oh + orow + n) = ph;
                    *(__nv_bfloat162*)(Ol + orow + n) = pl;
                }
            }
    } else {
        // channel-major fp32 via smem transpose (64 n-rows x 128 tokens), one pass
        float* sbuf = (float*)smem;
        __syncthreads();
        #pragma unroll
        for (int i = 0; i < 2; i++)
            #pragma unroll
            for (int j4 = 0; j4 < 4; j4++)
                #pragma unroll
                for (int rr = 0; rr < 2; rr++) {
                    int tok = mw*32 + i*16 + (lane >> 2) + rr*8;
                    int nl = nw*32 + j4*8 + 2*(lane & 3);
                    sbuf[nl*132 + tok]     = acc[i][j4][rr*2+0];
                    sbuf[(nl+1)*132 + tok] = acc[i][j4][rr*2+1];
                }
        __syncthreads();
        int row = tid >> 2;
        int n = n0 + row;
        if (n < bRows) {
            float bv = (EPT == EPT_BIAS) ? bias[n] : 0.f;
            const float* srcr = sbuf + row*132;
            float* dstr = outF + ((size_t)zb * bRows + n) * LSEQ + tl0;
            int c0 = (tid & 3) * 4;
            #pragma unroll
            for (int q = 0; q < 8; q++) {
                int col = c0 + q*16;
                float4 v = *(const float4*)(srcr + col);
                v.x += bv; v.y += bv; v.z += bv; v.w += bv;
                *(float4*)(dstr + col) = v;
            }
        }
    }
}

// ---------------- fused weight bf16 split (4 segments) ----------------
__global__ void wsplit4_k(const float* __restrict__ w0, const float* __restrict__ w1,
                          const float* __restrict__ w2, const float* __restrict__ w3,
                          __nv_bfloat16* __restrict__ h0, __nv_bfloat16* __restrict__ l0,
                          __nv_bfloat16* __restrict__ h1, __nv_bfloat16* __restrict__ l1,
                          __nv_bfloat16* __restrict__ h2, __nv_bfloat16* __restrict__ l2,
                          __nv_bfloat16* __restrict__ h3, __nv_bfloat16* __restrict__ l3)
{
    int seg = blockIdx.y;
    const float* w = seg==0?w0 : seg==1?w1 : seg==2?w2 : w3;
    __nv_bfloat16* h = seg==0?h0 : seg==1?h1 : seg==2?h2 : h3;
    __nv_bfloat16* l = seg==0?l0 : seg==1?l1 : seg==2?l2 : l3;
    int n = (seg < 3) ? 65536 : 307200;
    int i = blockIdx.x * blockDim.x + threadIdx.x;
    if (i < n) { __nv_bfloat16 hh, ll; bf16split(w[i], hh, ll); h[i] = hh; l[i] = ll; }
}

// ---------------- transpose input0 -> token-major fp32 ----------------
__global__ void xposeF_k(const float* __restrict__ in, float* __restrict__ out)
{
    __shared__ float t[32][33];
    int b = blockIdx.z;
    int tok0 = blockIdx.x * 32, ch0 = blockIdx.y * 32;
    int lx = threadIdx.x & 31, ly = threadIdx.x >> 5;
    #pragma unroll
    for (int i = 0; i < 4; i++) {
        int ch = ch0 + ly + i*8;
        t[lx][ly + i*8] = in[((size_t)b*256 + ch)*LSEQ + tok0 + lx];
    }
    __syncthreads();
    #pragma unroll
    for (int i = 0; i < 4; i++) {
        int tok = tok0 + ly + i*8;
        out[((size_t)b*LSEQ + tok)*256 + ch0 + lx] = t[ly + i*8][lx];
    }
}

// ---------------- layernorm -> token-major bf16 hi/lo ----------------
__global__ void ln_k(const float* __restrict__ in0, const float* __restrict__ in1,
                     const float* __restrict__ w0, const float* __restrict__ b0,
                     const float* __restrict__ w1, const float* __restrict__ b1,
                     __nv_bfloat16* __restrict__ s0h, __nv_bfloat16* __restrict__ s0l,
                     __nv_bfloat16* __restrict__ s1h, __nv_bfloat16* __restrict__ s1l)
{
    int which = blockIdx.y;
    const float* in = which ? in1 : in0;
    const float* w  = which ? w1  : w0;
    const float* bb = which ? b1  : b0;
    __nv_bfloat16* oh = which ? s1h : s0h;
    __nv_bfloat16* ol = which ? s1l : s0l;
    int idx = blockIdx.x * blockDim.x + threadIdx.x;
    int b = idx >> 12, l = idx & (LSEQ-1);
    const float* p = in + (size_t)b*DIMC*LSEQ + l;
    float s = 0.f, s2 = 0.f;
    #pragma unroll 8
    for (int c = 0; c < DIMC; c++) { float v = p[(size_t)c*LSEQ]; s += v; s2 += v*v; }
    float mean = s * (1.f/DIMC);
    float var  = s2 * (1.f/DIMC) - mean*mean;
    float rstd = rsqrtf(var + EPS_F);
    size_t ob = (size_t)idx * 256;
    for (int c0 = 0; c0 < DIMC; c0 += 8) {
        __align__(16) __nv_bfloat16 hh[8], ll[8];
        #pragma unroll
        for (int j = 0; j < 8; j++) {
            float v = (p[(size_t)(c0+j)*LSEQ] - mean) * rstd * w[c0+j] + bb[c0+j];
            bf16split(v, hh[j], ll[j]);
        }
        *(uint4*)(oh + ob + c0) = *(uint4*)hh;
        *(uint4*)(ol + ob + c0) = *(uint4*)ll;
    }
}

// ---------------- depthwise causal conv (K=4) + silu — both dirs ----------------
__global__ void conv_silu_k(const float* __restrict__ x,
                            const float* __restrict__ wf, const float* __restrict__ bf,
                            const float* __restrict__ wb, const float* __restrict__ bbias,
                            float* __restrict__ xc)
{
    int t   = blockIdx.x * blockDim.x + threadIdx.x;
    int bdd = blockIdx.y;                 // dir*512 + b*256 + d
    int dir = bdd >> 9;
    int bd  = bdd & 511;
    int d   = bd & 255;
    const float* w  = dir ? wb : wf;
    const float* bi = dir ? bbias : bf;
    const float* xp = x + (size_t)bd*LSEQ;
    float acc = bi[d];
    #pragma unroll
    for (int k = 0; k < 4; k++) {
        int s = t - 3 + k;
        if (s >= 0) {
            int ph = dir ? (LSEQ-1-s) : s;
            acc += w[d*4+k] * xp[ph];
        }
    }
    xc[(size_t)bdd*LSEQ + t] = acc * sigmoidf_(acc);
}

// ---------------- fp32 SGEMM (xproj / dtproj), per-dir weight select ----------------
enum { EP_NONE=0, EP_SPBIAS=1 };

template<int EP>
__global__ void __launch_bounds__(256) sgemm_k(
    const float* __restrict__ A0, const float* __restrict__ A1, int lda,
    const float* __restrict__ B, int ldb, long long bStride,
    float* __restrict__ C, int ldc, long long cStride,
    int M, int Kdim,
    const float* __restrict__ bias0, const float* __restrict__ bias1)
{
    __shared__ float As[8][128];
    __shared__ float Bs[8][128];
    int zb = blockIdx.z;
    int dir = zb >> 1;
    const float* A = dir ? A1 : A0;
    const float* bias = dir ? bias1 : bias0;
    B += (size_t)zb * bStride;
    C += (size_t)zb * cStride;

    int m0 = blockIdx.y * 128;
    int n0 = blockIdx.x * 128;
    int tid = threadIdx.x;
    int ar  = tid >> 1, ac = (tid & 1) << 2;
    int brr = tid >> 5, bc = (tid & 31) << 2;
    int mt0 = (tid >> 4) << 2, nt0 = (tid & 15) << 2;

    unsigned long long acc[8][4];
    #pragma unroll
    for (int i = 0; i < 8; i++)
        #pragma unroll
        for (int j = 0; j < 4; j++) acc[i][j] = 0ull;

    for (int k0 = 0; k0 < Kdim; k0 += 8) {
        float4 a4 = make_float4(0.f,0.f,0.f,0.f);
        int arow = m0 + ar;
        if (arow < M) a4 = *(const float4*)(A + (size_t)arow*lda + (k0 + ac));
        As[ac+0][ar] = a4.x; As[ac+1][ar] = a4.y; As[ac+2][ar] = a4.z; As[ac+3][ar] = a4.w;
        float4 b4 = *(const float4*)(B + (size_t)(k0 + brr)*ldb + (n0 + bc));
        *(float4*)&Bs[brr][bc] = b4;
        __syncthreads();
        #pragma unroll
        for (int kk = 0; kk < 8; kk++) {
            float4 aL = *(const float4*)&As[kk][mt0];
            float4 aH = *(const float4*)&As[kk][mt0+64];
            float av[8] = {aL.x,aL.y,aL.z,aL.w,aH.x,aH.y,aH.z,aH.w};
            unsigned long long b2[4];
            const unsigned long long* bpL = (const unsigned long long*)&Bs[kk][nt0];
            const unsigned long long* bpH = (const unsigned long long*)&Bs[kk][nt0+64];
            b2[0] = bpL[0]; b2[1] = bpL[1]; b2[2] = bpH[0]; b2[3] = bpH[1];
            #pragma unroll
            for (int i = 0; i < 8; i++) {
                unsigned long long a2;
                asm("mov.b64 %0, {%1, %1};" : "=l"(a2) : "f"(av[i]));
                #pragma unroll
                for (int j = 0; j < 4; j++)
                    asm("fma.rn.f32x2 %0, %1, %2, %0;" : "+l"(acc[i][j]) : "l"(a2), "l"(b2[j]));
            }
        }
        __syncthreads();
    }

    #pragma unroll
    for (int i = 0; i < 8; i++) {
        int m = m0 + ((i < 4) ? (mt0 + i) : (64 + mt0 + i - 4));
        if (m >= M) continue;
        float bv = (EP == EP_SPBIAS) ? bias[m] : 0.f;
        #pragma unroll
        for (int j = 0; j < 4; j++) {
            int n = n0 + ((j < 2) ? (nt0 + 2*j) : (64 + nt0 + 2*(j-2)));
            float2 v;
            asm("mov.b64 {%0, %1}, %2;" : "=f"(v.x), "=f"(v.y) : "l"(acc[i][j]));
            if (EP == EP_SPBIAS) { v.x = softplusf_(v.x + bv); v.y = softplusf_(v.y + bv); }
            *(float2*)(C + (size_t)m*ldc + n) = v;
        }
    }
}

// ---------------- chunked selective scan (both dirs in one launch) ----------------
__global__ void __launch_bounds__(256) scanA_k(
    const float* __restrict__ dt, const float* __restrict__ xc,
    const float* __restrict__ dbl,
    const float* __restrict__ A0, const float* __restrict__ A1,
    float* __restrict__ P, float* __restrict__ S)
{
    __shared__ float sdt[32][65], sx[32][65], sB[8][65];
    int chunk = blockIdx.x, zd = blockIdx.y, d0 = blockIdx.z * 32;
    int dir = zd >> 1, b = zd & 1;
    const float* Alog = dir ? A1 : A0;
    int tid = threadIdx.x;
    size_t base = ((size_t)(zd*DIMC + d0))*LSEQ + chunk*64;
    for (int i = tid; i < 2048; i += 256) {
        int r = i >> 6, c = i & 63;
        sdt[r][c] = dt[base + (size_t)r*LSEQ + c];
        sx [r][c] = xc[base + (size_t)r*LSEQ + c];
    }
    size_t bbase = ((size_t)(zd*32 + 16))*LSEQ + chunk*64;
    for (int i = tid; i < 512; i += 256) {
        int r = i >> 6, c = i & 63;
        sB[r][c] = dbl[bbase + (size_t)r*LSEQ + c];
    }
    __syncthreads();
    int dl = tid >> 3, n = tid & 7;
    float Aa = -__expf(Alog[(d0+dl)*8 + n]);
    float Pv = 1.f, Sv = 0.f;
    #pragma unroll 8
    for (int t = 0; t < 64; t++) {
        float dtv = sdt[dl][t];
        float dA  = __expf(dtv * Aa);
        Sv = Sv*dA + dtv * sx[dl][t] * sB[n][t];
        Pv *= dA;
    }
    size_t o = (size_t)dir*SCN_ + (((size_t)chunk*BATCH + b)*DIMC + d0+dl)*8 + n;
    P[o] = Pv; S[o] = Sv;
}

__global__ void scanB_k(const float* __restrict__ P, const float* __restrict__ S,
                        float* __restrict__ Hi)
{
    int gid = blockIdx.x * blockDim.x + threadIdx.x;   // 0..8191
    int dir = gid >> 12, idx = gid & 4095;
    const float* Pd = P + (size_t)dir*SCN_;
    const float* Sd = S + (size_t)dir*SCN_;
    float* Hd = Hi + (size_t)dir*SCN_;
    float h = 0.f;
    for (int c0 = 0; c0 < 64; c0 += 8) {
        float p[8], s[8];
        #pragma unroll
        for (int j = 0; j < 8; j++) {
            size_t o = (size_t)(c0+j)*4096 + idx;
            p[j] = Pd[o]; s[j] = Sd[o];
        }
        #pragma unroll
        for (int j = 0; j < 8; j++) {
            Hd[(size_t)(c0+j)*4096 + idx] = h;
            h = h * p[j] + s[j];
        }
    }
}

__global__ void __launch_bounds__(256) scanC_k(
    const float* __restrict__ dt, const float* __restrict__ xc,
    const float* __restrict__ dbl,
    const float* __restrict__ A0, const float* __restrict__ A1,
    const float* __restrict__ Hi,
    const float* __restrict__ D0, const float* __restrict__ D1,
    const float* __restrict__ z, float* __restrict__ y)
{
    __shared__ float sdt[32][65], sx[32][65], sB[8][65], sC[8][65];
    __shared__ float sy[32][64];
    int chunk = blockIdx.x, zd = blockIdx.y, d0 = blockIdx.z * 32;
    int dir = zd >> 1, b = zd & 1;
    const float* Alog = dir ? A1 : A0;
    const float* Dp   = dir ? D1 : D0;
    int tid = threadIdx.x;
    size_t base = ((size_t)(zd*DIMC + d0))*LSEQ + chunk*64;
    for (int i = tid; i < 2048; i += 256) {
        int r = i >> 6, c = i & 63;
        sdt[r][c] = dt[base + (size_t)r*LSEQ + c];
        sx [r][c] = xc[base + (size_t)r*LSEQ + c];
    }
    size_t bbase = ((size_t)(zd*32 + 16))*LSEQ + chunk*64;
    size_t cbase = ((size_t)(zd*32 + 24))*LSEQ + chunk*64;
    for (int i = tid; i < 512; i += 256) {
        int r = i >> 6, c = i & 63;
        sB[r][c] = dbl[bbase + (size_t)r*LSEQ + c];
        sC[r][c] = dbl[cbase + (size_t)r*LSEQ + c];
    }
    __syncthreads();
    int dl = tid >> 3, n = tid & 7;
    float Aa = -__expf(Alog[(d0+dl)*8 + n]);
    float h = Hi[(size_t)dir*SCN_ + (((size_t)chunk*BATCH + b)*DIMC + d0+dl)*8 + n];
    for (int t = 0; t < 64; t++) {
        float dtv = sdt[dl][t];
        float dA  = __expf(dtv * Aa);
        h = h*dA + dtv * sx[dl][t] * sB[n][t];
        float yv = h * sC[n][t];
        yv += __shfl_down_sync(0xffffffffu, yv, 4);
        yv += __shfl_down_sync(0xffffffffu, yv, 2);
        yv += __shfl_down_sync(0xffffffffu, yv, 1);
        if (n == 0) sy[dl][t] = yv;
    }
    __syncthreads();
    float* yD = y + (size_t)dir * BATCH*DIMC*LSEQ;
    for (int i = tid; i < 2048; i += 256) {
        int r = i >> 6, c = i & 63;
        int tl = chunk*64 + c;
        int lp = dir ? (LSEQ-1-tl) : tl;
        size_t gi = ((size_t)(b*DIMC + d0 + r))*LSEQ + lp;
        float v = sy[r][c] + sx[r][c]*Dp[d0+r];
        float zz = z[gi];
        yD[gi] = v * zz * sigmoidf_(zz);
    }
}

// ---------------- rmsnorm 3 heads -> token-major bf16 hi/lo ----------------
__global__ void rms3_k(const float* __restrict__ yf, const float* __restrict__ yb,
                       const float* __restrict__ w,
                       __nv_bfloat16* __restrict__ ynh, __nv_bfloat16* __restrict__ ynl)
{
    int idx = blockIdx.x * blockDim.x + threadIdx.x;
    int b = idx >> 12, l = idx & (LSEQ-1);
    size_t base = (size_t)b*DIMC*LSEQ + l;
    float sa = 0.f, sf = 0.f, sb = 0.f;
    #pragma unroll 8
    for (int d = 0; d < DIMC; d++) {
        float vf = yf[base + (size_t)d*LSEQ];
        float vb = yb[base + (size_t)d*LSEQ];
        float va = 0.5f*(vf+vb);
        sa += va*va; sf += vf*vf; sb += vb*vb;
    }
    float ra = rsqrtf(sa*(1.f/DIMC) + EPS_F);
    float rf = rsqrtf(sf*(1.f/DIMC) + EPS_F);
    float rb = rsqrtf(sb*(1.f/DIMC) + EPS_F);
    size_t r0 = ((size_t)(0*2 + b)*LSEQ + l) * 256;
    size_t r1 = ((size_t)(1*2 + b)*LSEQ + l) * 256;
    size_t r2 = ((size_t)(2*2 + b)*LSEQ + l) * 256;
    for (int d0 = 0; d0 < DIMC; d0 += 8) {
        __align__(16) __nv_bfloat16 h0[8], l0[8], h1[8], l1[8], h2[8], l2[8];
        #pragma unroll
        for (int j = 0; j < 8; j++) {
            int d = d0 + j;
            float vf = yf[base + (size_t)d*LSEQ];
            float vb = yb[base + (size_t)d*LSEQ];
            float va = 0.5f*(vf+vb);
            float ww = w[d];
            bf16split(va*ra*ww, h0[j], l0[j]);
            bf16split(vf*rf*ww, h1[j], l1[j]);
            bf16split(vb*rb*ww, h2[j], l2[j]);
        }
        *(uint4*)(ynh + r0 + d0) = *(uint4*)h0; *(uint4*)(ynl + r0 + d0) = *(uint4*)l0;
        *(uint4*)(ynh + r1 + d0) = *(uint4*)h1; *(uint4*)(ynl + r1 + d0) = *(uint4*)l1;
        *(uint4*)(ynh + r2 + d0) = *(uint4*)h2; *(uint4*)(ynl + r2 + d0) = *(uint4*)l2;
    }
}

// ---------------- launch ----------------
extern "C" void kernel_launch(void* const* d_in, const int* in_sizes, int n_in,
                              void* d_out, int out_size)
{
    (void)in_sizes; (void)n_in; (void)out_size;
    const float* input0      = (const float*)d_in[0];
    const float* input1      = (const float*)d_in[1];
    const float* norm0_w     = (const float*)d_in[2];
    const float* norm0_b     = (const float*)d_in[3];
    const float* norm1_w     = (const float*)d_in[4];
    const float* norm1_b     = (const float*)d_in[5];
    const float* in_proj_w   = (const float*)d_in[6];
    const float* in_projz_w  = (const float*)d_in[7];
    const float* conv1d_w    = (const float*)d_in[8];
    const float* conv1d_bias = (const float*)d_in[9];
    const float* conv1db_w   = (const float*)d_in[10];
    const float* conv1db_bias= (const float*)d_in[11];
    const float* xproj_w     = (const float*)d_in[12];
    const float* xprojb_w    = (const float*)d_in[13];
    const float* dtproj_w    = (const float*)d_in[14];
    const float* dtproj_bias = (const float*)d_in[15];
    const float* dtprojb_w   = (const float*)d_in[16];
    const float* dtprojb_bias= (const float*)d_in[17];
    const float* A_log       = (const float*)d_in[18];
    const float* Ab_log      = (const float*)d_in[19];
    const float* D_p         = (const float*)d_in[20];
    const float* D_b         = (const float*)d_in[21];
    const float* rms_w       = (const float*)d_in[22];
    const float* out_proj_w  = (const float*)d_in[23];
    const float* conv3d_w    = (const float*)d_in[24];
    const float* conv3d_bias = (const float*)d_in[25];
    float* out = (float*)d_out;

    float *x_, *z_, *xc_, *dbl_, *dt_, *P_, *S_, *Hi_, *y_, *skipT;
    __nv_bfloat16 *s0h,*s0l,*s1h,*s1l,*ynh,*ynl,*oh,*ol;
    __nv_bfloat16 *wip_h,*wip_l,*wiz_h,*wiz_l,*wop_h,*wop_l,*wc3_h,*wc3_l;
    cudaGetSymbolAddress((void**)&x_,   g_x);
    cudaGetSymbolAddress((void**)&z_,   g_z);
    cudaGetSymbolAddress((void**)&xc_,  g_xc);
    cudaGetSymbolAddress((void**)&dbl_, g_dbl);
    cudaGetSymbolAddress((void**)&dt_,  g_dt);
    cudaGetSymbolAddress((void**)&P_,   g_P);
    cudaGetSymbolAddress((void**)&S_,   g_S);
    cudaGetSymbolAddress((void**)&Hi_,  g_Hi);
    cudaGetSymbolAddress((void**)&y_,   g_y);
    cudaGetSymbolAddress((void**)&skipT,g_skipT);
    cudaGetSymbolAddress((void**)&s0h,  g_s0h);
    cudaGetSymbolAddress((void**)&s0l,  g_s0l);
    cudaGetSymbolAddress((void**)&s1h,  g_s1h);
    cudaGetSymbolAddress((void**)&s1l,  g_s1l);
    cudaGetSymbolAddress((void**)&ynh,  g_ynh);
    cudaGetSymbolAddress((void**)&ynl,  g_ynl);
    cudaGetSymbolAddress((void**)&oh,   g_oh);
    cudaGetSymbolAddress((void**)&ol,   g_ol);
    cudaGetSymbolAddress((void**)&wip_h, g_wip_h); cudaGetSymbolAddress((void**)&wip_l, g_wip_l);
    cudaGetSymbolAddress((void**)&wiz_h, g_wiz_h); cudaGetSymbolAddress((void**)&wiz_l, g_wiz_l);
    cudaGetSymbolAddress((void**)&wop_h, g_wop_h); cudaGetSymbolAddress((void**)&wop_l, g_wop_l);
    cudaGetSymbolAddress((void**)&wc3_h, g_wc3_h); cudaGetSymbolAddress((void**)&wc3_l, g_wc3_l);

    const int TCSMEM = 2 * STG;   // 110592 -> 2 CTAs/SM
    cudaFuncSetAttribute(tcgemm_k<EPT_XPOSE>, cudaFuncAttributeMaxDynamicSharedMemorySize, TCSMEM);
    cudaFuncSetAttribute(tcgemm_k<EPT_SKIP>,  cudaFuncAttributeMaxDynamicSharedMemorySize, TCSMEM);
    cudaFuncSetAttribute(tcgemm_k<EPT_BIAS>,  cudaFuncAttributeMaxDynamicSharedMemorySize, TCSMEM);

    const long long SB  = (long long)DIMC*LSEQ;
    const long long SB32= (long long)32*LSEQ;

    // 0) fused weight splits + skip transpose
    wsplit4_k<<<dim3(1200,4), 256>>>(in_proj_w, in_projz_w, out_proj_w, conv3d_w,
                                     wip_h, wip_l, wiz_h, wiz_l, wop_h, wop_l, wc3_h, wc3_l);
    xposeF_k<<<dim3(128,8,2), 256>>>(input0, skipT);

    // 1) layernorms -> token-major bf16 hi/lo
    ln_k<<<dim3(32,2), 256>>>(input0, input1, norm0_w, norm0_b, norm1_w, norm1_b,
                              s0h, s0l, s1h, s1l);

    // 2) in_proj / in_projz on tensor cores -> channel-major fp32
    tcgemm_k<EPT_XPOSE><<<dim3(4,32,2), 256, TCSMEM>>>(s0h, s0l, wip_h, wip_l, 256,
                                                       x_, nullptr, nullptr, nullptr, nullptr);
    tcgemm_k<EPT_XPOSE><<<dim3(4,32,2), 256, TCSMEM>>>(s1h, s1l, wiz_h, wiz_l, 256,
                                                       z_, nullptr, nullptr, nullptr, nullptr);

    // 3) conv + silu, both dirs
    conv_silu_k<<<dim3(16,1024), 256>>>(x_, conv1d_w, conv1d_bias, conv1db_w, conv1db_bias,
                                        (float*)xc_);
    // 4) xproj, both dirs
    sgemm_k<EP_NONE><<<dim3(32,1,4), 256>>>(xproj_w, xprojb_w, 256,
                                            xc_, LSEQ, SB, dbl_, LSEQ, SB32,
                                            32, 256, nullptr, nullptr);
    // 5) dtproj + softplus, both dirs
    sgemm_k<EP_SPBIAS><<<dim3(32,2,4), 256>>>(dtproj_w, dtprojb_w, 16,
                                              dbl_, LSEQ, SB32, dt_, LSEQ, SB,
                                              256, 16, dtproj_bias, dtprojb_bias);
    // 6) chunked scan, both dirs
    scanA_k<<<dim3(64,4,8), 256>>>(dt_, xc_, dbl_, A_log, Ab_log, P_, S_);
    scanB_k<<<32, 256>>>(P_, S_, Hi_);
    scanC_k<<<dim3(64,4,8), 256>>>(dt_, xc_, dbl_, A_log, Ab_log, Hi_, D_p, D_b, z_, y_);

    // 7) rmsnorm 3 heads
    rms3_k<<<32, 256>>>(y_, y_ + (size_t)BATCH*DIMC*LSEQ, rms_w, ynh, ynl);

    // 8) out_proj (+skip) -> token-major bf16 hi/lo
    tcgemm_k<EPT_SKIP><<<dim3(4,32,6), 256, TCSMEM>>>(ynh, ynl, wop_h, wop_l, 256,
                                                      nullptr, nullptr, skipT, oh, ol);

    // 9) conv3d (+bias) -> final output (channel-major fp32)
    tcgemm_k<EPT_BIAS><<<dim3(19,32,6), 256, TCSMEM>>>(oh, ol, wc3_h, wc3_l, 1200,
                                                       out, conv3d_bias, nullptr, nullptr, nullptr);
}